// round 12
// baseline (speedup 1.0000x reference)
#include <cuda_runtime.h>
#include <cuda_fp16.h>
#include <math.h>
#include <stdint.h>

// ---------------- problem constants ----------------
#define BATCH  4
#define MQ     1024
#define NKV    2048
#define DMODEL 1024
#define NHEAD  16
#define HDIM   64
#define DMLP   4096
#define ZHB    (NHEAD*BATCH)

typedef __half f16;

// ---------------- scratch (device globals; no allocs allowed) ----------------
__device__ __align__(1024) float g_resid[(size_t)BATCH*MQ*DMODEL];

__device__ __align__(1024) f16 g_qf [(size_t)BATCH*MQ*DMODEL];
__device__ __align__(1024) f16 g_xf [(size_t)BATCH*NKV*DMODEL];
__device__ __align__(1024) f16 g_wqf[(size_t)DMODEL*DMODEL];
__device__ __align__(1024) f16 g_wkf[(size_t)DMODEL*DMODEL];
__device__ __align__(1024) f16 g_wvf[(size_t)DMODEL*DMODEL];
__device__ __align__(1024) f16 g_wof[(size_t)DMODEL*DMODEL];
__device__ __align__(1024) f16 g_w1f[(size_t)DMLP*DMODEL];
__device__ __align__(1024) f16 g_w2f[(size_t)DMODEL*DMLP];
__device__ __align__(1024) f16 g_qpf[(size_t)BATCH*MQ*DMODEL];
__device__ __align__(1024) f16 g_kpf[(size_t)BATCH*NKV*DMODEL];
__device__ __align__(1024) f16 g_vtf[(size_t)ZHB*HDIM*NKV];
__device__ __align__(1024) f16 g_pf [(size_t)ZHB*MQ*NKV];     // 268 MB fp16 p
__device__ __align__(1024) f16 g_ctxf[(size_t)BATCH*MQ*DMODEL];
__device__ __align__(1024) f16 g_hf [(size_t)BATCH*MQ*DMODEL];
__device__ __align__(1024) f16 g_h1f[(size_t)BATCH*MQ*DMLP];

// ---------------- helpers ----------------
#define SW128(o) ((uint32_t)(o) ^ ((((uint32_t)(o)) >> 3) & 0x70u))

__device__ __forceinline__ uint32_t smem_u32(const void* p) {
    return (uint32_t)__cvta_generic_to_shared(p);
}

__device__ __forceinline__ void cp16(uint32_t dst, const void* src) {
    asm volatile("cp.async.cg.shared.global [%0], [%1], 16;" :: "r"(dst), "l"(src));
}
#define CP_COMMIT() asm volatile("cp.async.commit_group;" ::: "memory")
#define CP_WAIT0()  asm volatile("cp.async.wait_group 0;" ::: "memory")
#define CP_WAIT1()  asm volatile("cp.async.wait_group 1;" ::: "memory")
#define CP_WAIT2()  asm volatile("cp.async.wait_group 2;" ::: "memory")

#define LDSM4(r0, r1, r2, r3, addr) \
    asm volatile("ldmatrix.sync.aligned.m8n8.x4.shared.b16 {%0,%1,%2,%3}, [%4];" \
        : "=r"(r0), "=r"(r1), "=r"(r2), "=r"(r3) : "r"(addr))

__device__ __forceinline__ void mma_f16(float* c, const uint32_t* a, const uint32_t* b) {
    asm volatile(
        "mma.sync.aligned.m16n8k16.row.col.f32.f16.f16.f32 "
        "{%0,%1,%2,%3}, {%4,%5,%6,%7}, {%8,%9}, {%0,%1,%2,%3};"
        : "+f"(c[0]), "+f"(c[1]), "+f"(c[2]), "+f"(c[3])
        : "r"(a[0]), "r"(a[1]), "r"(a[2]), "r"(a[3]), "r"(b[0]), "r"(b[1]));
}

__device__ __forceinline__ float ex2(float x) {
    float r;
    asm("ex2.approx.f32 %0, %1;" : "=f"(r) : "f"(x));
    return r;
}

__device__ __forceinline__ float gelu_exact(float v) {
    return 0.5f * v * (1.0f + erff(v * 0.70710678118654752440f));
}

__device__ __forceinline__ uint32_t pack2h(float e0, float e1) {
    __half2 hp = __floats2half2_rn(e0, e1);
    return *reinterpret_cast<uint32_t*>(&hp);
}

// ============================================================================
//   single-term fp16 GEMM: A fp16, B fp16, fp32 accumulate.
//   TN=64, 256 threads, MI=2, 48KB stages.
// ============================================================================
#define DNT 256
#define DTN 64
#define OUT_F32ADD 0   // fp32, + Dadd
#define OUT_F16    1   // single fp16 (EPI==2 -> gelu)
#define OUT_VT     2   // transposed per-head single fp16 (V projection)

template<int EPI, int OUT>
__device__ void tc_gemm1(
    const f16* __restrict__ A, const f16* __restrict__ Bs,
    const float* __restrict__ bias, const float* __restrict__ Dadd,
    float* __restrict__ C, f16* __restrict__ Cf,
    int K, int lda, int ldb, int ldc, int ldd)
{
    extern __shared__ char smem[];
    constexpr int TN = DTN;
    constexpr int A_BYTES = 128 * 128;           // 16384
    constexpr int B_BYTES = TN * 128;            // 8192
    constexpr int STAGE   = A_BYTES + B_BYTES;   // 24576
    constexpr int MI = 2;

    const uint32_t sb = smem_u32(smem);
    const int tid  = threadIdx.x;
    const int wid  = tid >> 5;
    const int lane = tid & 31;
    const int m0 = blockIdx.y * 128;
    const int n0 = blockIdx.x * TN;
    const int wm0 = (wid / 2) * 32;
    const int wn0 = (wid % 2) * 32;

    float acc[MI][4][4];
    #pragma unroll
    for (int mi = 0; mi < MI; mi++)
        #pragma unroll
        for (int ni = 0; ni < 4; ni++)
            #pragma unroll
            for (int e = 0; e < 4; e++) acc[mi][ni][e] = 0.0f;

    auto load1 = [&](uint32_t st, long long kc) {
        #pragma unroll
        for (int it = 0; it < 4; it++) {
            int idx = tid + it * 256;
            int r = idx >> 3, c = idx & 7;
            uint32_t so = SW128(r * 128 + c * 16);
            cp16(st + so, A + (long long)(m0 + r) * lda + kc + c * 8);
        }
        #pragma unroll
        for (int it = 0; it < 2; it++) {
            int idx = tid + it * 256;
            int r = idx >> 3, c = idx & 7;
            uint32_t so = SW128(r * 128 + c * 16);
            cp16(st + A_BYTES + so, Bs + (long long)(n0 + r) * ldb + kc + c * 8);
        }
        CP_COMMIT();
    };

    const int NC = K >> 6;
    load1(sb, 0);
    if (NC > 1) load1(sb + STAGE, 64);

    for (int i = 0; i < NC; i++) {
        if (i + 1 < NC) { CP_WAIT1(); } else { CP_WAIT0(); }
        __syncthreads();

        const uint32_t st = sb + (i & 1) * STAGE;
        #pragma unroll
        for (int kk = 0; kk < 4; kk++) {
            uint32_t ah[MI][4], bh[4][2];
            const int colA = kk * 32 + ((lane & 16) ? 16 : 0);
            const int rA   = lane & 15;
            #pragma unroll
            for (int mi = 0; mi < MI; mi++) {
                uint32_t off = SW128((uint32_t)(wm0 + mi * 16 + rA) * 128 + colA);
                LDSM4(ah[mi][0], ah[mi][1], ah[mi][2], ah[mi][3], st + off);
            }
            const int colB = kk * 32 + ((lane & 8) ? 16 : 0);
            const int rB   = (lane & 7) + ((lane & 16) ? 8 : 0);
            #pragma unroll
            for (int nj = 0; nj < 2; nj++) {
                uint32_t off = SW128((uint32_t)(wn0 + nj * 16 + rB) * 128 + colB);
                LDSM4(bh[nj*2][0], bh[nj*2][1], bh[nj*2+1][0], bh[nj*2+1][1],
                      st + A_BYTES + off);
            }
            #pragma unroll
            for (int mi = 0; mi < MI; mi++)
                #pragma unroll
                for (int ni = 0; ni < 4; ni++)
                    mma_f16(acc[mi][ni], ah[mi], bh[ni]);
        }
        __syncthreads();
        if (i + 2 < NC) load1(sb + (i & 1) * STAGE, (long long)(i + 2) * 64);
    }

    constexpr int LDS = (OUT == OUT_VT) ? (TN + 1) : (TN + 8);
    float* sOut = (float*)smem;
    __syncthreads();

    #pragma unroll
    for (int mi = 0; mi < MI; mi++) {
        const int r0 = wm0 + mi * 16 + (lane >> 2);
        #pragma unroll
        for (int ni = 0; ni < 4; ni++) {
            const int c0 = wn0 + ni * 8 + (lane & 3) * 2;
            sOut[r0 * LDS + c0]           = acc[mi][ni][0];
            sOut[r0 * LDS + c0 + 1]       = acc[mi][ni][1];
            sOut[(r0 + 8) * LDS + c0]     = acc[mi][ni][2];
            sOut[(r0 + 8) * LDS + c0 + 1] = acc[mi][ni][3];
        }
    }
    __syncthreads();

    if (OUT == OUT_VT) {
        const int bb = m0 / NKV;
        const int nb = m0 % NKV;
        const int colw = tid >> 5;
        #pragma unroll
        for (int cp = 0; cp < 8; cp++) {
            const int col = colw + cp * 8;
            const int e = n0 + col;
            const int hh2 = e >> 6, dd = e & 63;
            const long long base =
                ((long long)(hh2 * BATCH + bb) * HDIM + dd) * NKV + nb;
            const float bv = bias[e];
            #pragma unroll
            for (int rh = 0; rh < 2; rh++) {
                const int row0 = rh * 64 + 2 * lane;
                const float v0 = sOut[row0       * LDS + col] + bv;
                const float v1 = sOut[(row0 + 1) * LDS + col] + bv;
                *(uint32_t*)(Cf + base + row0) = pack2h(v0, v1);
            }
        }
        return;
    }

    const int c = tid & (TN - 1);
    const int rs = tid / TN;
    const int n = n0 + c;
    #pragma unroll 4
    for (int rr = 0; rr < 128; rr += 4) {
        const int r = rr + rs;
        float v = sOut[r * LDS + c] + bias[n];
        const long long o = (long long)(m0 + r) * ldc + n;
        if (OUT == OUT_F32ADD) {
            C[o] = v + Dadd[(long long)(m0 + r) * ldd + n];
        } else {
            if (EPI == 2) v = gelu_exact(v);
            Cf[o] = __float2half_rn(v);
        }
    }
}

template<int EPI, int OUT>
__global__ void __launch_bounds__(DNT)
k_gemm(const f16* A, const f16* Bs,
       const float* bias, const float* Dadd,
       float* C, f16* Cf, int K, int ldc, int ldd)
{
    tc_gemm1<EPI, OUT>(A, Bs, bias, Dadd, C, Cf, K, K, K, ldc, ldd);
}

#define DSMEM1 (2 * (16384 + DTN * 128))   // 49152

// ============================================================================
//   fused attention, single-term fp16; p stored fp16 to scratch,
//   normalize tail reads fp16 p and emits fp32 attn.
// ============================================================================
#define ATTN_SMEM (16384 + 2*32768)   // Q + 2 stages x (K 16K + V 16K) = 81920
#define NCH (NKV/128)

__device__ __forceinline__ void load_kv(
    uint32_t st, const f16* __restrict__ kp, const f16* __restrict__ vt,
    int ci, int tid)
{
    #pragma unroll
    for (int it = 0; it < 4; it++) {
        int idx = tid + it * 256;
        int r = idx >> 3, c = idx & 7;
        uint32_t so = SW128((uint32_t)r * 128 + c * 16);
        cp16(st + so, kp + (long long)(ci * 128 + r) * DMODEL + c * 8);
    }
    #pragma unroll
    for (int it = 0; it < 4; it++) {
        int idx = tid + it * 256;
        int hf = idx >> 9, d = (idx >> 3) & 63, c = idx & 7;
        uint32_t so = (uint32_t)hf * 8192 + SW128((uint32_t)d * 128 + c * 16);
        cp16(st + 16384 + so, vt + (long long)d * NKV + ci * 128 + hf * 64 + c * 8);
    }
    CP_COMMIT();
}

__global__ void __launch_bounds__(256, 1)
k_attn(const f16* __restrict__ qpf, const f16* __restrict__ kpf,
       const f16* __restrict__ vtf,
       f16* __restrict__ pf, float* __restrict__ attn, f16* __restrict__ ctxf)
{
    extern __shared__ char smem[];
    const uint32_t sb = smem_u32(smem);
    const int tid = threadIdx.x, wid = tid >> 5, lane = tid & 31;
    const int z  = blockIdx.x;            // h*BATCH + b
    const int h  = z / BATCH, b = z % BATCH;
    const int m0 = blockIdx.y * 128;
    const int wm0 = wid * 16;

    const f16* khb = kpf + (long long)b * NKV * DMODEL + h * HDIM;
    const f16* vtb = vtf + (long long)z * HDIM * NKV;
    f16* pf_w = pf + ((long long)z * MQ + m0 + wm0) * NKV;

    const uint32_t sQ = sb;
    const uint32_t sS = sb + 16384;

    {
        const f16* q0 = qpf + ((long long)(b * MQ + m0)) * DMODEL + h * HDIM;
        #pragma unroll
        for (int it = 0; it < 4; it++) {
            int idx = tid + it * 256;
            int r = idx >> 3, c = idx & 7;
            uint32_t so = SW128((uint32_t)r * 128 + c * 16);
            cp16(sQ + so, q0 + (long long)r * DMODEL + c * 8);
        }
        CP_COMMIT();
    }
    load_kv(sS,         khb, vtb, 0, tid);
    load_kv(sS + 32768, khb, vtb, 1, tid);

    CP_WAIT2();
    __syncthreads();

    // preload Q fragments (persistent)
    uint32_t qf[4][4];
    {
        const int rA = lane & 15;
        #pragma unroll
        for (int kk = 0; kk < 4; kk++) {
            const int colA = kk * 32 + ((lane & 16) ? 16 : 0);
            uint32_t off = SW128((uint32_t)(wm0 + rA) * 128 + colA);
            LDSM4(qf[kk][0], qf[kk][1], qf[kk][2], qf[kk][3], sQ + off);
        }
    }

    float cacc[8][4];
    #pragma unroll
    for (int i = 0; i < 8; i++)
        #pragma unroll
        for (int e = 0; e < 4; e++) cacc[i][e] = 0.0f;
    float lp0 = 0.0f, lp1 = 0.0f;

    const int rB   = (lane & 7) + ((lane & 16) ? 8 : 0);
    const int r    = lane >> 2;
    const int c2   = (lane & 3) * 2;
    const float CE = 0.125f * 1.4426950408889634f;

    for (int ci = 0; ci < NCH; ci++) {
        if (ci + 1 < NCH) { CP_WAIT1(); } else { CP_WAIT0(); }
        __syncthreads();
        const uint32_t st = sS + (ci & 1) * 32768;

        // ---- S = Q K^T ----
        float sacc[16][4];
        #pragma unroll
        for (int t = 0; t < 16; t++)
            #pragma unroll
            for (int e = 0; e < 4; e++) sacc[t][e] = 0.0f;

        #pragma unroll
        for (int kk = 0; kk < 4; kk++) {
            const int colB = kk * 32 + ((lane & 8) ? 16 : 0);
            #pragma unroll
            for (int nt = 0; nt < 8; nt++) {
                uint32_t off = SW128((uint32_t)(nt * 16 + rB) * 128 + colB);
                uint32_t bh[4];
                LDSM4(bh[0], bh[1], bh[2], bh[3], st + off);
                mma_f16(sacc[2*nt],   qf[kk], bh);
                mma_f16(sacc[2*nt+1], qf[kk], bh + 2);
            }
        }

        // ---- p = exp(S/8) -> packed fp16; write scratch; row sums ----
        uint32_t pk[16][2];
        f16* a0 = pf_w + (long long)r * NKV + ci * 128;
        f16* a1 = a0 + 8 * NKV;
        #pragma unroll
        for (int t = 0; t < 16; t++) {
            float p0 = ex2(sacc[t][0] * CE);
            float p1 = ex2(sacc[t][1] * CE);
            float p2 = ex2(sacc[t][2] * CE);
            float p3 = ex2(sacc[t][3] * CE);
            lp0 += p0 + p1;  lp1 += p2 + p3;
            pk[t][0] = pack2h(p0, p1);
            pk[t][1] = pack2h(p2, p3);
            *(uint32_t*)(a0 + t * 8 + c2) = pk[t][0];
            *(uint32_t*)(a1 + t * 8 + c2) = pk[t][1];
        }

        // ---- ctx += P V (reuse packed fragments) ----
        #pragma unroll
        for (int ks = 0; ks < 8; ks++) {
            uint32_t ah[4];
            ah[0] = pk[2*ks][0];
            ah[1] = pk[2*ks][1];
            ah[2] = pk[2*ks+1][0];
            ah[3] = pk[2*ks+1][1];

            const int hf = ks >> 2;
            const int colB = (ks & 3) * 32 + ((lane & 8) ? 16 : 0);
            const uint32_t v_base = st + 16384 + hf * 8192;
            #pragma unroll
            for (int dt = 0; dt < 4; dt++) {
                uint32_t off = SW128((uint32_t)(dt * 16 + rB) * 128 + colB);
                uint32_t bh[4];
                LDSM4(bh[0], bh[1], bh[2], bh[3], v_base + off);
                mma_f16(cacc[2*dt],   ah, bh);
                mma_f16(cacc[2*dt+1], ah, bh + 2);
            }
        }

        __syncthreads();
        if (ci + 2 < NCH)
            load_kv(sS + (ci & 1) * 32768, khb, vtb, ci + 2, tid);
    }

    // ---- row sums -> inverse; ctx write; normalize fp16 p -> fp32 attn ----
    lp0 += __shfl_xor_sync(0xFFFFFFFFu, lp0, 1);
    lp0 += __shfl_xor_sync(0xFFFFFFFFu, lp0, 2);
    lp1 += __shfl_xor_sync(0xFFFFFFFFu, lp1, 1);
    lp1 += __shfl_xor_sync(0xFFFFFFFFu, lp1, 2);
    const float il0 = 1.0f / lp0, il1 = 1.0f / lp1;

    float* ssum = (float*)smem;          // stage smem retired
    if ((lane & 3) == 0) {
        ssum[wm0 + r]     = il0;
        ssum[wm0 + r + 8] = il1;
    }

    const long long cb = ((long long)(b * MQ + m0 + wm0)) * DMODEL + h * HDIM;
    #pragma unroll
    for (int dt = 0; dt < 8; dt++) {
        const int d0 = dt * 8 + c2;
        *(uint32_t*)(ctxf + cb + (long long)r * DMODEL + d0) =
            pack2h(cacc[dt][0] * il0, cacc[dt][1] * il0);
        *(uint32_t*)(ctxf + cb + (long long)(r + 8) * DMODEL + d0) =
            pack2h(cacc[dt][2] * il1, cacc[dt][3] * il1);
    }

    __syncthreads();   // orders p-writes + ssum for all warps

    const f16* pb = pf + ((long long)z * MQ + m0) * NKV;
    float* ab = attn + ((long long)z * MQ + m0) * NKV;
    for (int rr = 0; rr < 128; rr += 8) {
        const int row = rr + wid;
        const float s = ssum[row];
        const uint32_t* ph = (const uint32_t*)(pb + (long long)row * NKV);
        float4* p4 = (float4*)(ab + (long long)row * NKV);
        #pragma unroll
        for (int j = 0; j < 16; j++) {
            uint32_t w0 = ph[2 * (lane + 32 * j)];
            uint32_t w1 = ph[2 * (lane + 32 * j) + 1];
            __half2 h0 = *reinterpret_cast<__half2*>(&w0);
            __half2 h1 = *reinterpret_cast<__half2*>(&w1);
            float4 v;
            v.x = __half2float(__low2half(h0))  * s;
            v.y = __half2float(__high2half(h0)) * s;
            v.z = __half2float(__low2half(h1))  * s;
            v.w = __half2float(__high2half(h1)) * s;
            p4[lane + 32 * j] = v;
        }
    }
}

// ---------------- fp32 -> single fp16 ----------------
__global__ void __launch_bounds__(256)
k_cvt16(const float* __restrict__ x, f16* __restrict__ o)
{
    const long long i = ((long long)blockIdx.x * 256 + threadIdx.x) * 4;
    const float4 v = *(const float4*)(x + i);
    __half2 p0 = __floats2half2_rn(v.x, v.y);
    __half2 p1 = __floats2half2_rn(v.z, v.w);
    *(uint32_t*)(o + i)     = *reinterpret_cast<uint32_t*>(&p0);
    *(uint32_t*)(o + i + 2) = *reinterpret_cast<uint32_t*>(&p1);
}

// ---------------- layernorm -> single fp16 ----------------
__global__ void __launch_bounds__(256)
k_ln(const float* __restrict__ x, const float* __restrict__ g,
     const float* __restrict__ b, f16* __restrict__ o)
{
    __shared__ float r1[256], r2[256];
    const long long row = blockIdx.x;
    const float* p = x + row * (long long)DMODEL;
    const int t = threadIdx.x;

    float v[4]; float s = 0.0f, s2 = 0.0f;
    #pragma unroll
    for (int i = 0; i < 4; i++) {
        v[i] = p[t + i * 256];
        s += v[i]; s2 += v[i] * v[i];
    }
    r1[t] = s; r2[t] = s2; __syncthreads();
    for (int st = 128; st > 0; st >>= 1) {
        if (t < st) { r1[t] += r1[t + st]; r2[t] += r2[t + st]; }
        __syncthreads();
    }
    const float mu  = r1[0] * (1.0f / DMODEL);
    const float var = r2[0] * (1.0f / DMODEL) - mu * mu;
    const float inv = rsqrtf(var + 1e-5f);

    f16* po = o + row * (long long)DMODEL;
    #pragma unroll
    for (int i = 0; i < 4; i++) {
        const int c = t + i * 256;
        po[c] = __float2half_rn((v[i] - mu) * inv * g[c] + b[c]);
    }
}

// ---------------- host launch ----------------
static void* sym(const void* s) { void* p; cudaGetSymbolAddress(&p, s); return p; }

extern "C" void kernel_launch(void* const* d_in, const int* in_sizes, int n_in,
                              void* d_out, int out_size)
{
    const float* x    = (const float*)d_in[0];
    const float* q    = (const float*)d_in[1];
    const float* w_q  = (const float*)d_in[2];
    const float* b_q  = (const float*)d_in[3];
    const float* w_k  = (const float*)d_in[4];
    const float* b_k  = (const float*)d_in[5];
    const float* w_v  = (const float*)d_in[6];
    const float* b_v  = (const float*)d_in[7];
    const float* w_o  = (const float*)d_in[8];
    const float* b_o  = (const float*)d_in[9];
    const float* ln2g = (const float*)d_in[10];
    const float* ln2b = (const float*)d_in[11];
    const float* w1   = (const float*)d_in[12];
    const float* b1   = (const float*)d_in[13];
    const float* w2   = (const float*)d_in[14];
    const float* b2   = (const float*)d_in[15];

    float* out  = (float*)d_out;
    float* attn = out + (long long)BATCH * MQ * DMODEL;

    float* resid = (float*)sym(g_resid);
    f16 *qf=(f16*)sym(g_qf), *xf=(f16*)sym(g_xf);
    f16 *wqf=(f16*)sym(g_wqf), *wkf=(f16*)sym(g_wkf);
    f16 *wvf=(f16*)sym(g_wvf), *wof=(f16*)sym(g_wof);
    f16 *w1f=(f16*)sym(g_w1f), *w2f=(f16*)sym(g_w2f);
    f16 *qpf=(f16*)sym(g_qpf), *kpf=(f16*)sym(g_kpf), *vtf=(f16*)sym(g_vtf);
    f16 *pf=(f16*)sym(g_pf);
    f16 *ctxf=(f16*)sym(g_ctxf);
    f16 *hf=(f16*)sym(g_hf), *h1f=(f16*)sym(g_h1f);

    cudaFuncSetAttribute((const void*)k_gemm<0,OUT_F16>,   cudaFuncAttributeMaxDynamicSharedMemorySize, DSMEM1);
    cudaFuncSetAttribute((const void*)k_gemm<2,OUT_F16>,   cudaFuncAttributeMaxDynamicSharedMemorySize, DSMEM1);
    cudaFuncSetAttribute((const void*)k_gemm<0,OUT_VT>,    cudaFuncAttributeMaxDynamicSharedMemorySize, DSMEM1);
    cudaFuncSetAttribute((const void*)k_gemm<0,OUT_F32ADD>,cudaFuncAttributeMaxDynamicSharedMemorySize, DSMEM1);
    cudaFuncSetAttribute((const void*)k_attn, cudaFuncAttributeMaxDynamicSharedMemorySize, ATTN_SMEM);

    const dim3 blk(256);
    const dim3 dblk(DNT);
    #define C16(src, dst, nelem) k_cvt16<<<(int)((nelem) / 1024), blk>>>(src, dst)

    // conversions
    C16(x,   xf,  (size_t)BATCH*NKV*DMODEL);
    C16(w_v, wvf, (size_t)DMODEL*DMODEL);
    C16(w_k, wkf, (size_t)DMODEL*DMODEL);
    C16(q,   qf,  (size_t)BATCH*MQ*DMODEL);
    C16(w_q, wqf, (size_t)DMODEL*DMODEL);

    // V projection -> transposed single fp16
    k_gemm<0,OUT_VT><<<dim3(DMODEL/DTN, 64), dblk, DSMEM1>>>(xf, wvf, b_v, nullptr,
        nullptr, vtf, DMODEL, 0, 0);
    // K projection -> single fp16
    k_gemm<0,OUT_F16><<<dim3(DMODEL/DTN, 64), dblk, DSMEM1>>>(xf, wkf, b_k, nullptr,
        nullptr, kpf, DMODEL, DMODEL, 0);
    // Q projection -> single fp16
    k_gemm<0,OUT_F16><<<dim3(DMODEL/DTN, 32), dblk, DSMEM1>>>(qf, wqf, b_q, nullptr,
        nullptr, qpf, DMODEL, DMODEL, 0);

    // fused attention
    k_attn<<<dim3(ZHB, MQ/128), blk, ATTN_SMEM>>>(qpf, kpf, vtf, pf, attn, ctxf);

    // remaining weight conversions
    C16(w_o, wof, (size_t)DMODEL*DMODEL);
    C16(w1,  w1f, (size_t)DMLP*DMODEL);
    C16(w2,  w2f, (size_t)DMODEL*DMLP);

    // resid = ctx @ w_o^T + b_o + q
    k_gemm<0,OUT_F32ADD><<<dim3(DMODEL/DTN, 32), dblk, DSMEM1>>>(ctxf, wof, b_o, q,
        resid, nullptr, DMODEL, DMODEL, DMODEL);

    // h = LN(resid) -> fp16
    k_ln<<<BATCH*MQ, blk>>>(resid, ln2g, ln2b, hf);

    // h1 = gelu(h @ w1^T + b1) -> fp16
    k_gemm<2,OUT_F16><<<dim3(DMLP/DTN, 32), dblk, DSMEM1>>>(hf, w1f, b1, nullptr,
        nullptr, h1f, DMODEL, DMLP, 0);

    // out = h1 @ w2^T + b2 + resid
    k_gemm<0,OUT_F32ADD><<<dim3(DMODEL/DTN, 32), dblk, DSMEM1>>>(h1f, w2f, b2, resid,
        out, nullptr, DMLP, DMODEL, DMODEL);

    #undef C16
}

// round 13
// speedup vs baseline: 1.4338x; 1.4338x over previous
#include <cuda_runtime.h>
#include <cuda_fp16.h>
#include <math.h>
#include <stdint.h>

// ---------------- problem constants ----------------
#define BATCH  4
#define MQ     1024
#define NKV    2048
#define DMODEL 1024
#define NHEAD  16
#define HDIM   64
#define DMLP   4096
#define ZHB    (NHEAD*BATCH)

typedef __half f16;

// ---------------- scratch (device globals; no allocs allowed) ----------------
__device__ __align__(1024) float g_resid[(size_t)BATCH*MQ*DMODEL];

__device__ __align__(1024) f16 g_qf [(size_t)BATCH*MQ*DMODEL];
__device__ __align__(1024) f16 g_xf [(size_t)BATCH*NKV*DMODEL];
__device__ __align__(1024) f16 g_wqf[(size_t)DMODEL*DMODEL];
__device__ __align__(1024) f16 g_wkf[(size_t)DMODEL*DMODEL];
__device__ __align__(1024) f16 g_wvf[(size_t)DMODEL*DMODEL];
__device__ __align__(1024) f16 g_wof[(size_t)DMODEL*DMODEL];
__device__ __align__(1024) f16 g_w1f[(size_t)DMLP*DMODEL];
__device__ __align__(1024) f16 g_w2f[(size_t)DMODEL*DMLP];
__device__ __align__(1024) f16 g_qpf[(size_t)BATCH*MQ*DMODEL];
__device__ __align__(1024) f16 g_kpf[(size_t)BATCH*NKV*DMODEL];
__device__ __align__(1024) f16 g_vtf[(size_t)ZHB*HDIM*NKV];
__device__ __align__(1024) f16 g_ctxf[(size_t)BATCH*MQ*DMODEL];
__device__ __align__(1024) f16 g_hf [(size_t)BATCH*MQ*DMODEL];
__device__ __align__(1024) f16 g_h1f[(size_t)BATCH*MQ*DMLP];

// ---------------- helpers ----------------
#define SW128(o) ((uint32_t)(o) ^ ((((uint32_t)(o)) >> 3) & 0x70u))

__device__ __forceinline__ uint32_t smem_u32(const void* p) {
    return (uint32_t)__cvta_generic_to_shared(p);
}

__device__ __forceinline__ void cp16(uint32_t dst, const void* src) {
    asm volatile("cp.async.cg.shared.global [%0], [%1], 16;" :: "r"(dst), "l"(src));
}
#define CP_COMMIT() asm volatile("cp.async.commit_group;" ::: "memory")
#define CP_WAIT0()  asm volatile("cp.async.wait_group 0;" ::: "memory")
#define CP_WAIT1()  asm volatile("cp.async.wait_group 1;" ::: "memory")
#define CP_WAIT2()  asm volatile("cp.async.wait_group 2;" ::: "memory")

#define LDSM4(r0, r1, r2, r3, addr) \
    asm volatile("ldmatrix.sync.aligned.m8n8.x4.shared.b16 {%0,%1,%2,%3}, [%4];" \
        : "=r"(r0), "=r"(r1), "=r"(r2), "=r"(r3) : "r"(addr))

__device__ __forceinline__ void mma_f16(float* c, const uint32_t* a, const uint32_t* b) {
    asm volatile(
        "mma.sync.aligned.m16n8k16.row.col.f32.f16.f16.f32 "
        "{%0,%1,%2,%3}, {%4,%5,%6,%7}, {%8,%9}, {%0,%1,%2,%3};"
        : "+f"(c[0]), "+f"(c[1]), "+f"(c[2]), "+f"(c[3])
        : "r"(a[0]), "r"(a[1]), "r"(a[2]), "r"(a[3]), "r"(b[0]), "r"(b[1]));
}

__device__ __forceinline__ float ex2(float x) {
    float r;
    asm("ex2.approx.f32 %0, %1;" : "=f"(r) : "f"(x));
    return r;
}

__device__ __forceinline__ float gelu_exact(float v) {
    return 0.5f * v * (1.0f + erff(v * 0.70710678118654752440f));
}

__device__ __forceinline__ uint32_t pack2h(float e0, float e1) {
    __half2 hp = __floats2half2_rn(e0, e1);
    return *reinterpret_cast<uint32_t*>(&hp);
}

// ============================================================================
//   single-term fp16 GEMM: A fp16, B fp16, fp32 accumulate.
//   TN=64, 256 threads, MI=2, 48KB stages.  (unchanged from round 11)
// ============================================================================
#define DNT 256
#define DTN 64
#define OUT_F32ADD 0
#define OUT_F16    1
#define OUT_VT     2

template<int EPI, int OUT>
__device__ void tc_gemm1(
    const f16* __restrict__ A, const f16* __restrict__ Bs,
    const float* __restrict__ bias, const float* __restrict__ Dadd,
    float* __restrict__ C, f16* __restrict__ Cf,
    int K, int lda, int ldb, int ldc, int ldd)
{
    extern __shared__ char smem[];
    constexpr int TN = DTN;
    constexpr int A_BYTES = 128 * 128;
    constexpr int B_BYTES = TN * 128;
    constexpr int STAGE   = A_BYTES + B_BYTES;
    constexpr int MI = 2;

    const uint32_t sb = smem_u32(smem);
    const int tid  = threadIdx.x;
    const int wid  = tid >> 5;
    const int lane = tid & 31;
    const int m0 = blockIdx.y * 128;
    const int n0 = blockIdx.x * TN;
    const int wm0 = (wid / 2) * 32;
    const int wn0 = (wid % 2) * 32;

    float acc[MI][4][4];
    #pragma unroll
    for (int mi = 0; mi < MI; mi++)
        #pragma unroll
        for (int ni = 0; ni < 4; ni++)
            #pragma unroll
            for (int e = 0; e < 4; e++) acc[mi][ni][e] = 0.0f;

    auto load1 = [&](uint32_t st, long long kc) {
        #pragma unroll
        for (int it = 0; it < 4; it++) {
            int idx = tid + it * 256;
            int r = idx >> 3, c = idx & 7;
            uint32_t so = SW128(r * 128 + c * 16);
            cp16(st + so, A + (long long)(m0 + r) * lda + kc + c * 8);
        }
        #pragma unroll
        for (int it = 0; it < 2; it++) {
            int idx = tid + it * 256;
            int r = idx >> 3, c = idx & 7;
            uint32_t so = SW128(r * 128 + c * 16);
            cp16(st + A_BYTES + so, Bs + (long long)(n0 + r) * ldb + kc + c * 8);
        }
        CP_COMMIT();
    };

    const int NC = K >> 6;
    load1(sb, 0);
    if (NC > 1) load1(sb + STAGE, 64);

    for (int i = 0; i < NC; i++) {
        if (i + 1 < NC) { CP_WAIT1(); } else { CP_WAIT0(); }
        __syncthreads();

        const uint32_t st = sb + (i & 1) * STAGE;
        #pragma unroll
        for (int kk = 0; kk < 4; kk++) {
            uint32_t ah[MI][4], bh[4][2];
            const int colA = kk * 32 + ((lane & 16) ? 16 : 0);
            const int rA   = lane & 15;
            #pragma unroll
            for (int mi = 0; mi < MI; mi++) {
                uint32_t off = SW128((uint32_t)(wm0 + mi * 16 + rA) * 128 + colA);
                LDSM4(ah[mi][0], ah[mi][1], ah[mi][2], ah[mi][3], st + off);
            }
            const int colB = kk * 32 + ((lane & 8) ? 16 : 0);
            const int rB   = (lane & 7) + ((lane & 16) ? 8 : 0);
            #pragma unroll
            for (int nj = 0; nj < 2; nj++) {
                uint32_t off = SW128((uint32_t)(wn0 + nj * 16 + rB) * 128 + colB);
                LDSM4(bh[nj*2][0], bh[nj*2][1], bh[nj*2+1][0], bh[nj*2+1][1],
                      st + A_BYTES + off);
            }
            #pragma unroll
            for (int mi = 0; mi < MI; mi++)
                #pragma unroll
                for (int ni = 0; ni < 4; ni++)
                    mma_f16(acc[mi][ni], ah[mi], bh[ni]);
        }
        __syncthreads();
        if (i + 2 < NC) load1(sb + (i & 1) * STAGE, (long long)(i + 2) * 64);
    }

    constexpr int LDS = (OUT == OUT_VT) ? (TN + 1) : (TN + 8);
    float* sOut = (float*)smem;
    __syncthreads();

    #pragma unroll
    for (int mi = 0; mi < MI; mi++) {
        const int r0 = wm0 + mi * 16 + (lane >> 2);
        #pragma unroll
        for (int ni = 0; ni < 4; ni++) {
            const int c0 = wn0 + ni * 8 + (lane & 3) * 2;
            sOut[r0 * LDS + c0]           = acc[mi][ni][0];
            sOut[r0 * LDS + c0 + 1]       = acc[mi][ni][1];
            sOut[(r0 + 8) * LDS + c0]     = acc[mi][ni][2];
            sOut[(r0 + 8) * LDS + c0 + 1] = acc[mi][ni][3];
        }
    }
    __syncthreads();

    if (OUT == OUT_VT) {
        const int bb = m0 / NKV;
        const int nb = m0 % NKV;
        const int colw = tid >> 5;
        #pragma unroll
        for (int cp = 0; cp < 8; cp++) {
            const int col = colw + cp * 8;
            const int e = n0 + col;
            const int hh2 = e >> 6, dd = e & 63;
            const long long base =
                ((long long)(hh2 * BATCH + bb) * HDIM + dd) * NKV + nb;
            const float bv = bias[e];
            #pragma unroll
            for (int rh = 0; rh < 2; rh++) {
                const int row0 = rh * 64 + 2 * lane;
                const float v0 = sOut[row0       * LDS + col] + bv;
                const float v1 = sOut[(row0 + 1) * LDS + col] + bv;
                *(uint32_t*)(Cf + base + row0) = pack2h(v0, v1);
            }
        }
        return;
    }

    const int c = tid & (TN - 1);
    const int rs = tid / TN;
    const int n = n0 + c;
    #pragma unroll 4
    for (int rr = 0; rr < 128; rr += 4) {
        const int r = rr + rs;
        float v = sOut[r * LDS + c] + bias[n];
        const long long o = (long long)(m0 + r) * ldc + n;
        if (OUT == OUT_F32ADD) {
            C[o] = v + Dadd[(long long)(m0 + r) * ldd + n];
        } else {
            if (EPI == 2) v = gelu_exact(v);
            Cf[o] = __float2half_rn(v);
        }
    }
}

template<int EPI, int OUT>
__global__ void __launch_bounds__(DNT)
k_gemm(const f16* A, const f16* Bs,
       const float* bias, const float* Dadd,
       float* C, f16* Cf, int K, int ldc, int ldd)
{
    tc_gemm1<EPI, OUT>(A, Bs, bias, Dadd, C, Cf, K, K, K, ldc, ldd);
}

#define DSMEM1 (2 * (16384 + DTN * 128))   // 49152

// ============================================================================
//   fused attention, single-term fp16, register-thrifty interleaved S/PV:
//   per 16-col block nt: S MMAs -> exp -> fp32 p store -> pack -> PV MMAs.
//   2 CTAs/SM (launch_bounds(256,2)); numerics identical to round 11.
// ============================================================================
#define ATTN_SMEM (16384 + 2*32768)   // Q + 2 stages x (K 16K + V 16K) = 81920
#define NCH (NKV/128)

__device__ __forceinline__ void load_kv(
    uint32_t st, const f16* __restrict__ kp, const f16* __restrict__ vt,
    int ci, int tid)
{
    #pragma unroll
    for (int it = 0; it < 4; it++) {
        int idx = tid + it * 256;
        int r = idx >> 3, c = idx & 7;
        uint32_t so = SW128((uint32_t)r * 128 + c * 16);
        cp16(st + so, kp + (long long)(ci * 128 + r) * DMODEL + c * 8);
    }
    #pragma unroll
    for (int it = 0; it < 4; it++) {
        int idx = tid + it * 256;
        int hf = idx >> 9, d = (idx >> 3) & 63, c = idx & 7;
        uint32_t so = (uint32_t)hf * 8192 + SW128((uint32_t)d * 128 + c * 16);
        cp16(st + 16384 + so, vt + (long long)d * NKV + ci * 128 + hf * 64 + c * 8);
    }
    CP_COMMIT();
}

__global__ void __launch_bounds__(256, 2)
k_attn(const f16* __restrict__ qpf, const f16* __restrict__ kpf,
       const f16* __restrict__ vtf,
       float* __restrict__ attn, f16* __restrict__ ctxf)
{
    extern __shared__ char smem[];
    const uint32_t sb = smem_u32(smem);
    const int tid = threadIdx.x, wid = tid >> 5, lane = tid & 31;
    const int z  = blockIdx.x;            // h*BATCH + b
    const int h  = z / BATCH, b = z % BATCH;
    const int m0 = blockIdx.y * 128;
    const int wm0 = wid * 16;

    const f16* khb = kpf + (long long)b * NKV * DMODEL + h * HDIM;
    const f16* vtb = vtf + (long long)z * HDIM * NKV;
    float* attn_w = attn + ((long long)z * MQ + m0 + wm0) * NKV;

    const uint32_t sQ = sb;
    const uint32_t sS = sb + 16384;

    {
        const f16* q0 = qpf + ((long long)(b * MQ + m0)) * DMODEL + h * HDIM;
        #pragma unroll
        for (int it = 0; it < 4; it++) {
            int idx = tid + it * 256;
            int r = idx >> 3, c = idx & 7;
            uint32_t so = SW128((uint32_t)r * 128 + c * 16);
            cp16(sQ + so, q0 + (long long)r * DMODEL + c * 8);
        }
        CP_COMMIT();
    }
    load_kv(sS,         khb, vtb, 0, tid);
    load_kv(sS + 32768, khb, vtb, 1, tid);

    CP_WAIT2();
    __syncthreads();

    // preload Q fragments (persistent)
    uint32_t qf[4][4];
    {
        const int rA = lane & 15;
        #pragma unroll
        for (int kk = 0; kk < 4; kk++) {
            const int colA = kk * 32 + ((lane & 16) ? 16 : 0);
            uint32_t off = SW128((uint32_t)(wm0 + rA) * 128 + colA);
            LDSM4(qf[kk][0], qf[kk][1], qf[kk][2], qf[kk][3], sQ + off);
        }
    }

    float cacc[8][4];
    #pragma unroll
    for (int i = 0; i < 8; i++)
        #pragma unroll
        for (int e = 0; e < 4; e++) cacc[i][e] = 0.0f;
    float lp0 = 0.0f, lp1 = 0.0f;

    const int rB   = (lane & 7) + ((lane & 16) ? 8 : 0);
    const int r    = lane >> 2;
    const int c2   = (lane & 3) * 2;
    const float CE = 0.125f * 1.4426950408889634f;

    for (int ci = 0; ci < NCH; ci++) {
        if (ci + 1 < NCH) { CP_WAIT1(); } else { CP_WAIT0(); }
        __syncthreads();
        const uint32_t st = sS + (ci & 1) * 32768;
        float* a0 = attn_w + (long long)r * NKV + ci * 128;
        float* a1 = a0 + 8 * NKV;

        // interleaved: for each 16-column block nt, do S, exp/store, PV
        #pragma unroll
        for (int nt = 0; nt < 8; nt++) {
            // ---- S block: 2 accumulators over kk ----
            float s0[4] = {0.f, 0.f, 0.f, 0.f};
            float s1[4] = {0.f, 0.f, 0.f, 0.f};
            #pragma unroll
            for (int kk = 0; kk < 4; kk++) {
                const int colB = kk * 32 + ((lane & 8) ? 16 : 0);
                uint32_t off = SW128((uint32_t)(nt * 16 + rB) * 128 + colB);
                uint32_t bh[4];
                LDSM4(bh[0], bh[1], bh[2], bh[3], st + off);
                mma_f16(s0, qf[kk], bh);
                mma_f16(s1, qf[kk], bh + 2);
            }

            // ---- p = exp(S/8); store fp32; row sums; pack fragments ----
            const float p0 = ex2(s0[0] * CE), p1 = ex2(s0[1] * CE);
            const float p2 = ex2(s0[2] * CE), p3 = ex2(s0[3] * CE);
            const float p4 = ex2(s1[0] * CE), p5 = ex2(s1[1] * CE);
            const float p6 = ex2(s1[2] * CE), p7 = ex2(s1[3] * CE);
            lp0 += p0 + p1 + p4 + p5;
            lp1 += p2 + p3 + p6 + p7;
            *(float2*)(a0 + (2*nt)   * 8 + c2) = make_float2(p0, p1);
            *(float2*)(a1 + (2*nt)   * 8 + c2) = make_float2(p2, p3);
            *(float2*)(a0 + (2*nt+1) * 8 + c2) = make_float2(p4, p5);
            *(float2*)(a1 + (2*nt+1) * 8 + c2) = make_float2(p6, p7);

            uint32_t ah[4];
            ah[0] = pack2h(p0, p1);
            ah[1] = pack2h(p2, p3);
            ah[2] = pack2h(p4, p5);
            ah[3] = pack2h(p6, p7);

            // ---- PV block (ks == nt) ----
            const int hf = nt >> 2;
            const int colB = (nt & 3) * 32 + ((lane & 8) ? 16 : 0);
            const uint32_t v_base = st + 16384 + hf * 8192;
            #pragma unroll
            for (int dt = 0; dt < 4; dt++) {
                uint32_t off = SW128((uint32_t)(dt * 16 + rB) * 128 + colB);
                uint32_t bh[4];
                LDSM4(bh[0], bh[1], bh[2], bh[3], v_base + off);
                mma_f16(cacc[2*dt],   ah, bh);
                mma_f16(cacc[2*dt+1], ah, bh + 2);
            }
        }

        __syncthreads();
        if (ci + 2 < NCH)
            load_kv(sS + (ci & 1) * 32768, khb, vtb, ci + 2, tid);
    }

    // ---- row sums -> inverse; ctx write; in-kernel attn normalize ----
    lp0 += __shfl_xor_sync(0xFFFFFFFFu, lp0, 1);
    lp0 += __shfl_xor_sync(0xFFFFFFFFu, lp0, 2);
    lp1 += __shfl_xor_sync(0xFFFFFFFFu, lp1, 1);
    lp1 += __shfl_xor_sync(0xFFFFFFFFu, lp1, 2);
    const float il0 = 1.0f / lp0, il1 = 1.0f / lp1;

    float* ssum = (float*)smem;          // stage smem retired
    if ((lane & 3) == 0) {
        ssum[wm0 + r]     = il0;
        ssum[wm0 + r + 8] = il1;
    }

    const long long cb = ((long long)(b * MQ + m0 + wm0)) * DMODEL + h * HDIM;
    #pragma unroll
    for (int dt = 0; dt < 8; dt++) {
        const int d0 = dt * 8 + c2;
        *(uint32_t*)(ctxf + cb + (long long)r * DMODEL + d0) =
            pack2h(cacc[dt][0] * il0, cacc[dt][1] * il0);
        *(uint32_t*)(ctxf + cb + (long long)(r + 8) * DMODEL + d0) =
            pack2h(cacc[dt][2] * il1, cacc[dt][3] * il1);
    }

    __syncthreads();   // orders p-writes + ssum for all warps

    float* ab = attn + ((long long)z * MQ + m0) * NKV;
    for (int rr = 0; rr < 128; rr += 8) {
        const int row = rr + wid;
        const float s = ssum[row];
        float4* p4 = (float4*)(ab + (long long)row * NKV);
        #pragma unroll
        for (int j = 0; j < 16; j++) {
            float4 v = p4[lane + 32 * j];
            v.x *= s; v.y *= s; v.z *= s; v.w *= s;
            p4[lane + 32 * j] = v;
        }
    }
}

// ---------------- fp32 -> single fp16 ----------------
__global__ void __launch_bounds__(256)
k_cvt16(const float* __restrict__ x, f16* __restrict__ o)
{
    const long long i = ((long long)blockIdx.x * 256 + threadIdx.x) * 4;
    const float4 v = *(const float4*)(x + i);
    __half2 p0 = __floats2half2_rn(v.x, v.y);
    __half2 p1 = __floats2half2_rn(v.z, v.w);
    *(uint32_t*)(o + i)     = *reinterpret_cast<uint32_t*>(&p0);
    *(uint32_t*)(o + i + 2) = *reinterpret_cast<uint32_t*>(&p1);
}

// ---------------- layernorm -> single fp16 ----------------
__global__ void __launch_bounds__(256)
k_ln(const float* __restrict__ x, const float* __restrict__ g,
     const float* __restrict__ b, f16* __restrict__ o)
{
    __shared__ float r1[256], r2[256];
    const long long row = blockIdx.x;
    const float* p = x + row * (long long)DMODEL;
    const int t = threadIdx.x;

    float v[4]; float s = 0.0f, s2 = 0.0f;
    #pragma unroll
    for (int i = 0; i < 4; i++) {
        v[i] = p[t + i * 256];
        s += v[i]; s2 += v[i] * v[i];
    }
    r1[t] = s; r2[t] = s2; __syncthreads();
    for (int st = 128; st > 0; st >>= 1) {
        if (t < st) { r1[t] += r1[t + st]; r2[t] += r2[t + st]; }
        __syncthreads();
    }
    const float mu  = r1[0] * (1.0f / DMODEL);
    const float var = r2[0] * (1.0f / DMODEL) - mu * mu;
    const float inv = rsqrtf(var + 1e-5f);

    f16* po = o + row * (long long)DMODEL;
    #pragma unroll
    for (int i = 0; i < 4; i++) {
        const int c = t + i * 256;
        po[c] = __float2half_rn((v[i] - mu) * inv * g[c] + b[c]);
    }
}

// ---------------- host launch ----------------
static void* sym(const void* s) { void* p; cudaGetSymbolAddress(&p, s); return p; }

extern "C" void kernel_launch(void* const* d_in, const int* in_sizes, int n_in,
                              void* d_out, int out_size)
{
    const float* x    = (const float*)d_in[0];
    const float* q    = (const float*)d_in[1];
    const float* w_q  = (const float*)d_in[2];
    const float* b_q  = (const float*)d_in[3];
    const float* w_k  = (const float*)d_in[4];
    const float* b_k  = (const float*)d_in[5];
    const float* w_v  = (const float*)d_in[6];
    const float* b_v  = (const float*)d_in[7];
    const float* w_o  = (const float*)d_in[8];
    const float* b_o  = (const float*)d_in[9];
    const float* ln2g = (const float*)d_in[10];
    const float* ln2b = (const float*)d_in[11];
    const float* w1   = (const float*)d_in[12];
    const float* b1   = (const float*)d_in[13];
    const float* w2   = (const float*)d_in[14];
    const float* b2   = (const float*)d_in[15];

    float* out  = (float*)d_out;
    float* attn = out + (long long)BATCH * MQ * DMODEL;

    float* resid = (float*)sym(g_resid);
    f16 *qf=(f16*)sym(g_qf), *xf=(f16*)sym(g_xf);
    f16 *wqf=(f16*)sym(g_wqf), *wkf=(f16*)sym(g_wkf);
    f16 *wvf=(f16*)sym(g_wvf), *wof=(f16*)sym(g_wof);
    f16 *w1f=(f16*)sym(g_w1f), *w2f=(f16*)sym(g_w2f);
    f16 *qpf=(f16*)sym(g_qpf), *kpf=(f16*)sym(g_kpf), *vtf=(f16*)sym(g_vtf);
    f16 *ctxf=(f16*)sym(g_ctxf);
    f16 *hf=(f16*)sym(g_hf), *h1f=(f16*)sym(g_h1f);

    cudaFuncSetAttribute((const void*)k_gemm<0,OUT_F16>,   cudaFuncAttributeMaxDynamicSharedMemorySize, DSMEM1);
    cudaFuncSetAttribute((const void*)k_gemm<2,OUT_F16>,   cudaFuncAttributeMaxDynamicSharedMemorySize, DSMEM1);
    cudaFuncSetAttribute((const void*)k_gemm<0,OUT_VT>,    cudaFuncAttributeMaxDynamicSharedMemorySize, DSMEM1);
    cudaFuncSetAttribute((const void*)k_gemm<0,OUT_F32ADD>,cudaFuncAttributeMaxDynamicSharedMemorySize, DSMEM1);
    cudaFuncSetAttribute((const void*)k_attn, cudaFuncAttributeMaxDynamicSharedMemorySize, ATTN_SMEM);

    const dim3 blk(256);
    const dim3 dblk(DNT);
    #define C16(src, dst, nelem) k_cvt16<<<(int)((nelem) / 1024), blk>>>(src, dst)

    // conversions
    C16(x,   xf,  (size_t)BATCH*NKV*DMODEL);
    C16(w_v, wvf, (size_t)DMODEL*DMODEL);
    C16(w_k, wkf, (size_t)DMODEL*DMODEL);
    C16(q,   qf,  (size_t)BATCH*MQ*DMODEL);
    C16(w_q, wqf, (size_t)DMODEL*DMODEL);

    // V projection -> transposed single fp16
    k_gemm<0,OUT_VT><<<dim3(DMODEL/DTN, 64), dblk, DSMEM1>>>(xf, wvf, b_v, nullptr,
        nullptr, vtf, DMODEL, 0, 0);
    // K projection -> single fp16
    k_gemm<0,OUT_F16><<<dim3(DMODEL/DTN, 64), dblk, DSMEM1>>>(xf, wkf, b_k, nullptr,
        nullptr, kpf, DMODEL, DMODEL, 0);
    // Q projection -> single fp16
    k_gemm<0,OUT_F16><<<dim3(DMODEL/DTN, 32), dblk, DSMEM1>>>(qf, wqf, b_q, nullptr,
        nullptr, qpf, DMODEL, DMODEL, 0);

    // fused attention
    k_attn<<<dim3(ZHB, MQ/128), blk, ATTN_SMEM>>>(qpf, kpf, vtf, attn, ctxf);

    // remaining weight conversions
    C16(w_o, wof, (size_t)DMODEL*DMODEL);
    C16(w1,  w1f, (size_t)DMLP*DMODEL);
    C16(w2,  w2f, (size_t)DMODEL*DMLP);

    // resid = ctx @ w_o^T + b_o + q
    k_gemm<0,OUT_F32ADD><<<dim3(DMODEL/DTN, 32), dblk, DSMEM1>>>(ctxf, wof, b_o, q,
        resid, nullptr, DMODEL, DMODEL, DMODEL);

    // h = LN(resid) -> fp16
    k_ln<<<BATCH*MQ, blk>>>(resid, ln2g, ln2b, hf);

    // h1 = gelu(h @ w1^T + b1) -> fp16
    k_gemm<2,OUT_F16><<<dim3(DMLP/DTN, 32), dblk, DSMEM1>>>(hf, w1f, b1, nullptr,
        nullptr, h1f, DMODEL, DMLP, 0);

    // out = h1 @ w2^T + b2 + resid
    k_gemm<0,OUT_F32ADD><<<dim3(DMODEL/DTN, 32), dblk, DSMEM1>>>(h1f, w2f, b2, resid,
        out, nullptr, DMLP, DMODEL, DMODEL);

    #undef C16
}

// round 14
// speedup vs baseline: 1.6106x; 1.1234x over previous
#include <cuda_runtime.h>
#include <cuda_fp16.h>
#include <math.h>
#include <stdint.h>

// ---------------- problem constants ----------------
#define BATCH  4
#define MQ     1024
#define NKV    2048
#define DMODEL 1024
#define NHEAD  16
#define HDIM   64
#define DMLP   4096
#define ZHB    (NHEAD*BATCH)

typedef __half f16;

// ---------------- scratch (device globals; no allocs allowed) ----------------
__device__ __align__(1024) float g_resid[(size_t)BATCH*MQ*DMODEL];

__device__ __align__(1024) f16 g_qf [(size_t)BATCH*MQ*DMODEL];
__device__ __align__(1024) f16 g_xf [(size_t)BATCH*NKV*DMODEL];
__device__ __align__(1024) f16 g_wqf[(size_t)DMODEL*DMODEL];
__device__ __align__(1024) f16 g_wkf[(size_t)DMODEL*DMODEL];
__device__ __align__(1024) f16 g_wvf[(size_t)DMODEL*DMODEL];
__device__ __align__(1024) f16 g_wof[(size_t)DMODEL*DMODEL];
__device__ __align__(1024) f16 g_w1f[(size_t)DMLP*DMODEL];
__device__ __align__(1024) f16 g_w2f[(size_t)DMODEL*DMLP];
__device__ __align__(1024) f16 g_qpf[(size_t)BATCH*MQ*DMODEL];
__device__ __align__(1024) f16 g_kpf[(size_t)BATCH*NKV*DMODEL];
__device__ __align__(1024) f16 g_vtf[(size_t)ZHB*HDIM*NKV];
__device__ __align__(1024) f16 g_ctxf[(size_t)BATCH*MQ*DMODEL];
__device__ __align__(1024) f16 g_hf [(size_t)BATCH*MQ*DMODEL];
__device__ __align__(1024) f16 g_h1f[(size_t)BATCH*MQ*DMLP];

// ---------------- helpers ----------------
#define SW128(o) ((uint32_t)(o) ^ ((((uint32_t)(o)) >> 3) & 0x70u))

__device__ __forceinline__ uint32_t smem_u32(const void* p) {
    return (uint32_t)__cvta_generic_to_shared(p);
}

__device__ __forceinline__ void cp16(uint32_t dst, const void* src) {
    asm volatile("cp.async.cg.shared.global [%0], [%1], 16;" :: "r"(dst), "l"(src));
}
#define CP_COMMIT() asm volatile("cp.async.commit_group;" ::: "memory")
#define CP_WAIT0()  asm volatile("cp.async.wait_group 0;" ::: "memory")
#define CP_WAIT1()  asm volatile("cp.async.wait_group 1;" ::: "memory")
#define CP_WAIT2()  asm volatile("cp.async.wait_group 2;" ::: "memory")

#define LDSM4(r0, r1, r2, r3, addr) \
    asm volatile("ldmatrix.sync.aligned.m8n8.x4.shared.b16 {%0,%1,%2,%3}, [%4];" \
        : "=r"(r0), "=r"(r1), "=r"(r2), "=r"(r3) : "r"(addr))

__device__ __forceinline__ void mma_f16(float* c, const uint32_t* a, const uint32_t* b) {
    asm volatile(
        "mma.sync.aligned.m16n8k16.row.col.f32.f16.f16.f32 "
        "{%0,%1,%2,%3}, {%4,%5,%6,%7}, {%8,%9}, {%0,%1,%2,%3};"
        : "+f"(c[0]), "+f"(c[1]), "+f"(c[2]), "+f"(c[3])
        : "r"(a[0]), "r"(a[1]), "r"(a[2]), "r"(a[3]), "r"(b[0]), "r"(b[1]));
}

__device__ __forceinline__ float ex2(float x) {
    float r;
    asm("ex2.approx.f32 %0, %1;" : "=f"(r) : "f"(x));
    return r;
}

__device__ __forceinline__ float gelu_exact(float v) {
    return 0.5f * v * (1.0f + erff(v * 0.70710678118654752440f));
}

__device__ __forceinline__ uint32_t pack2h(float e0, float e1) {
    __half2 hp = __floats2half2_rn(e0, e1);
    return *reinterpret_cast<uint32_t*>(&hp);
}

// ============================================================================
//   single-term fp16 GEMM (unchanged from round 13)
// ============================================================================
#define DNT 256
#define DTN 64
#define OUT_F32ADD 0
#define OUT_F16    1
#define OUT_VT     2

template<int EPI, int OUT>
__device__ void tc_gemm1(
    const f16* __restrict__ A, const f16* __restrict__ Bs,
    const float* __restrict__ bias, const float* __restrict__ Dadd,
    float* __restrict__ C, f16* __restrict__ Cf,
    int K, int lda, int ldb, int ldc, int ldd)
{
    extern __shared__ char smem[];
    constexpr int TN = DTN;
    constexpr int A_BYTES = 128 * 128;
    constexpr int B_BYTES = TN * 128;
    constexpr int STAGE   = A_BYTES + B_BYTES;
    constexpr int MI = 2;

    const uint32_t sb = smem_u32(smem);
    const int tid  = threadIdx.x;
    const int wid  = tid >> 5;
    const int lane = tid & 31;
    const int m0 = blockIdx.y * 128;
    const int n0 = blockIdx.x * TN;
    const int wm0 = (wid / 2) * 32;
    const int wn0 = (wid % 2) * 32;

    float acc[MI][4][4];
    #pragma unroll
    for (int mi = 0; mi < MI; mi++)
        #pragma unroll
        for (int ni = 0; ni < 4; ni++)
            #pragma unroll
            for (int e = 0; e < 4; e++) acc[mi][ni][e] = 0.0f;

    auto load1 = [&](uint32_t st, long long kc) {
        #pragma unroll
        for (int it = 0; it < 4; it++) {
            int idx = tid + it * 256;
            int r = idx >> 3, c = idx & 7;
            uint32_t so = SW128(r * 128 + c * 16);
            cp16(st + so, A + (long long)(m0 + r) * lda + kc + c * 8);
        }
        #pragma unroll
        for (int it = 0; it < 2; it++) {
            int idx = tid + it * 256;
            int r = idx >> 3, c = idx & 7;
            uint32_t so = SW128(r * 128 + c * 16);
            cp16(st + A_BYTES + so, Bs + (long long)(n0 + r) * ldb + kc + c * 8);
        }
        CP_COMMIT();
    };

    const int NC = K >> 6;
    load1(sb, 0);
    if (NC > 1) load1(sb + STAGE, 64);

    for (int i = 0; i < NC; i++) {
        if (i + 1 < NC) { CP_WAIT1(); } else { CP_WAIT0(); }
        __syncthreads();

        const uint32_t st = sb + (i & 1) * STAGE;
        #pragma unroll
        for (int kk = 0; kk < 4; kk++) {
            uint32_t ah[MI][4], bh[4][2];
            const int colA = kk * 32 + ((lane & 16) ? 16 : 0);
            const int rA   = lane & 15;
            #pragma unroll
            for (int mi = 0; mi < MI; mi++) {
                uint32_t off = SW128((uint32_t)(wm0 + mi * 16 + rA) * 128 + colA);
                LDSM4(ah[mi][0], ah[mi][1], ah[mi][2], ah[mi][3], st + off);
            }
            const int colB = kk * 32 + ((lane & 8) ? 16 : 0);
            const int rB   = (lane & 7) + ((lane & 16) ? 8 : 0);
            #pragma unroll
            for (int nj = 0; nj < 2; nj++) {
                uint32_t off = SW128((uint32_t)(wn0 + nj * 16 + rB) * 128 + colB);
                LDSM4(bh[nj*2][0], bh[nj*2][1], bh[nj*2+1][0], bh[nj*2+1][1],
                      st + A_BYTES + off);
            }
            #pragma unroll
            for (int mi = 0; mi < MI; mi++)
                #pragma unroll
                for (int ni = 0; ni < 4; ni++)
                    mma_f16(acc[mi][ni], ah[mi], bh[ni]);
        }
        __syncthreads();
        if (i + 2 < NC) load1(sb + (i & 1) * STAGE, (long long)(i + 2) * 64);
    }

    constexpr int LDS = (OUT == OUT_VT) ? (TN + 1) : (TN + 8);
    float* sOut = (float*)smem;
    __syncthreads();

    #pragma unroll
    for (int mi = 0; mi < MI; mi++) {
        const int r0 = wm0 + mi * 16 + (lane >> 2);
        #pragma unroll
        for (int ni = 0; ni < 4; ni++) {
            const int c0 = wn0 + ni * 8 + (lane & 3) * 2;
            sOut[r0 * LDS + c0]           = acc[mi][ni][0];
            sOut[r0 * LDS + c0 + 1]       = acc[mi][ni][1];
            sOut[(r0 + 8) * LDS + c0]     = acc[mi][ni][2];
            sOut[(r0 + 8) * LDS + c0 + 1] = acc[mi][ni][3];
        }
    }
    __syncthreads();

    if (OUT == OUT_VT) {
        const int bb = m0 / NKV;
        const int nb = m0 % NKV;
        const int colw = tid >> 5;
        #pragma unroll
        for (int cp = 0; cp < 8; cp++) {
            const int col = colw + cp * 8;
            const int e = n0 + col;
            const int hh2 = e >> 6, dd = e & 63;
            const long long base =
                ((long long)(hh2 * BATCH + bb) * HDIM + dd) * NKV + nb;
            const float bv = bias[e];
            #pragma unroll
            for (int rh = 0; rh < 2; rh++) {
                const int row0 = rh * 64 + 2 * lane;
                const float v0 = sOut[row0       * LDS + col] + bv;
                const float v1 = sOut[(row0 + 1) * LDS + col] + bv;
                *(uint32_t*)(Cf + base + row0) = pack2h(v0, v1);
            }
        }
        return;
    }

    const int c = tid & (TN - 1);
    const int rs = tid / TN;
    const int n = n0 + c;
    #pragma unroll 4
    for (int rr = 0; rr < 128; rr += 4) {
        const int r = rr + rs;
        float v = sOut[r * LDS + c] + bias[n];
        const long long o = (long long)(m0 + r) * ldc + n;
        if (OUT == OUT_F32ADD) {
            C[o] = v + Dadd[(long long)(m0 + r) * ldd + n];
        } else {
            if (EPI == 2) v = gelu_exact(v);
            Cf[o] = __float2half_rn(v);
        }
    }
}

template<int EPI, int OUT>
__global__ void __launch_bounds__(DNT)
k_gemm(const f16* A, const f16* Bs,
       const float* bias, const float* Dadd,
       float* C, f16* Cf, int K, int ldc, int ldd)
{
    tc_gemm1<EPI, OUT>(A, Bs, bias, Dadd, C, Cf, K, K, K, ldc, ldd);
}

#define DSMEM1 (2 * (16384 + DTN * 128))   // 49152

// ============================================================================
//   fused two-pass attention, single-term fp16:
//   pass A: S -> exp -> lp, PV (no attn writes);  il kept in registers;
//   pass B: reload K only, recompute S, write exp(S)*il directly to attn.
//   Numerics identical to round 13.
// ============================================================================
#define ATTN_SMEM (16384 + 2*32768)   // Q + 2 stages x (K 16K + V 16K) = 81920
#define NCH (NKV/128)

__device__ __forceinline__ void load_kv(
    uint32_t st, const f16* __restrict__ kp, const f16* __restrict__ vt,
    int ci, int tid)
{
    #pragma unroll
    for (int it = 0; it < 4; it++) {
        int idx = tid + it * 256;
        int r = idx >> 3, c = idx & 7;
        uint32_t so = SW128((uint32_t)r * 128 + c * 16);
        cp16(st + so, kp + (long long)(ci * 128 + r) * DMODEL + c * 8);
    }
    #pragma unroll
    for (int it = 0; it < 4; it++) {
        int idx = tid + it * 256;
        int hf = idx >> 9, d = (idx >> 3) & 63, c = idx & 7;
        uint32_t so = (uint32_t)hf * 8192 + SW128((uint32_t)d * 128 + c * 16);
        cp16(st + 16384 + so, vt + (long long)d * NKV + ci * 128 + hf * 64 + c * 8);
    }
    CP_COMMIT();
}

__device__ __forceinline__ void load_k(
    uint32_t st, const f16* __restrict__ kp, int ci, int tid)
{
    #pragma unroll
    for (int it = 0; it < 4; it++) {
        int idx = tid + it * 256;
        int r = idx >> 3, c = idx & 7;
        uint32_t so = SW128((uint32_t)r * 128 + c * 16);
        cp16(st + so, kp + (long long)(ci * 128 + r) * DMODEL + c * 8);
    }
    CP_COMMIT();
}

__global__ void __launch_bounds__(256, 2)
k_attn(const f16* __restrict__ qpf, const f16* __restrict__ kpf,
       const f16* __restrict__ vtf,
       float* __restrict__ attn, f16* __restrict__ ctxf)
{
    extern __shared__ char smem[];
    const uint32_t sb = smem_u32(smem);
    const int tid = threadIdx.x, wid = tid >> 5, lane = tid & 31;
    const int z  = blockIdx.x;            // h*BATCH + b
    const int h  = z / BATCH, b = z % BATCH;
    const int m0 = blockIdx.y * 128;
    const int wm0 = wid * 16;

    const f16* khb = kpf + (long long)b * NKV * DMODEL + h * HDIM;
    const f16* vtb = vtf + (long long)z * HDIM * NKV;
    float* attn_w = attn + ((long long)z * MQ + m0 + wm0) * NKV;

    const uint32_t sQ = sb;
    const uint32_t sS = sb + 16384;

    {
        const f16* q0 = qpf + ((long long)(b * MQ + m0)) * DMODEL + h * HDIM;
        #pragma unroll
        for (int it = 0; it < 4; it++) {
            int idx = tid + it * 256;
            int r = idx >> 3, c = idx & 7;
            uint32_t so = SW128((uint32_t)r * 128 + c * 16);
            cp16(sQ + so, q0 + (long long)r * DMODEL + c * 8);
        }
        CP_COMMIT();
    }
    load_kv(sS,         khb, vtb, 0, tid);
    load_kv(sS + 32768, khb, vtb, 1, tid);

    CP_WAIT2();
    __syncthreads();

    // preload Q fragments (persistent across both passes)
    uint32_t qf[4][4];
    {
        const int rA = lane & 15;
        #pragma unroll
        for (int kk = 0; kk < 4; kk++) {
            const int colA = kk * 32 + ((lane & 16) ? 16 : 0);
            uint32_t off = SW128((uint32_t)(wm0 + rA) * 128 + colA);
            LDSM4(qf[kk][0], qf[kk][1], qf[kk][2], qf[kk][3], sQ + off);
        }
    }

    float cacc[8][4];
    #pragma unroll
    for (int i = 0; i < 8; i++)
        #pragma unroll
        for (int e = 0; e < 4; e++) cacc[i][e] = 0.0f;
    float lp0 = 0.0f, lp1 = 0.0f;

    const int rB   = (lane & 7) + ((lane & 16) ? 8 : 0);
    const int r    = lane >> 2;
    const int c2   = (lane & 3) * 2;
    const float CE = 0.125f * 1.4426950408889634f;

    // ======================= pass A: lp + PV =======================
    for (int ci = 0; ci < NCH; ci++) {
        if (ci + 1 < NCH) { CP_WAIT1(); } else { CP_WAIT0(); }
        __syncthreads();
        const uint32_t st = sS + (ci & 1) * 32768;

        #pragma unroll
        for (int nt = 0; nt < 8; nt++) {
            float s0[4] = {0.f, 0.f, 0.f, 0.f};
            float s1[4] = {0.f, 0.f, 0.f, 0.f};
            #pragma unroll
            for (int kk = 0; kk < 4; kk++) {
                const int colB = kk * 32 + ((lane & 8) ? 16 : 0);
                uint32_t off = SW128((uint32_t)(nt * 16 + rB) * 128 + colB);
                uint32_t bh[4];
                LDSM4(bh[0], bh[1], bh[2], bh[3], st + off);
                mma_f16(s0, qf[kk], bh);
                mma_f16(s1, qf[kk], bh + 2);
            }

            const float p0 = ex2(s0[0] * CE), p1 = ex2(s0[1] * CE);
            const float p2 = ex2(s0[2] * CE), p3 = ex2(s0[3] * CE);
            const float p4 = ex2(s1[0] * CE), p5 = ex2(s1[1] * CE);
            const float p6 = ex2(s1[2] * CE), p7 = ex2(s1[3] * CE);
            lp0 += p0 + p1 + p4 + p5;
            lp1 += p2 + p3 + p6 + p7;

            uint32_t ah[4];
            ah[0] = pack2h(p0, p1);
            ah[1] = pack2h(p2, p3);
            ah[2] = pack2h(p4, p5);
            ah[3] = pack2h(p6, p7);

            const int hf = nt >> 2;
            const int colB = (nt & 3) * 32 + ((lane & 8) ? 16 : 0);
            const uint32_t v_base = st + 16384 + hf * 8192;
            #pragma unroll
            for (int dt = 0; dt < 4; dt++) {
                uint32_t off = SW128((uint32_t)(dt * 16 + rB) * 128 + colB);
                uint32_t bh[4];
                LDSM4(bh[0], bh[1], bh[2], bh[3], v_base + off);
                mma_f16(cacc[2*dt],   ah, bh);
                mma_f16(cacc[2*dt+1], ah, bh + 2);
            }
        }

        __syncthreads();
        if (ci + 2 < NCH)
            load_kv(sS + (ci & 1) * 32768, khb, vtb, ci + 2, tid);
    }

    // ---- row sums -> inverses (stay in registers); write ctx ----
    lp0 += __shfl_xor_sync(0xFFFFFFFFu, lp0, 1);
    lp0 += __shfl_xor_sync(0xFFFFFFFFu, lp0, 2);
    lp1 += __shfl_xor_sync(0xFFFFFFFFu, lp1, 1);
    lp1 += __shfl_xor_sync(0xFFFFFFFFu, lp1, 2);
    const float il0 = 1.0f / lp0, il1 = 1.0f / lp1;

    const long long cb = ((long long)(b * MQ + m0 + wm0)) * DMODEL + h * HDIM;
    #pragma unroll
    for (int dt = 0; dt < 8; dt++) {
        const int d0 = dt * 8 + c2;
        *(uint32_t*)(ctxf + cb + (long long)r * DMODEL + d0) =
            pack2h(cacc[dt][0] * il0, cacc[dt][1] * il0);
        *(uint32_t*)(ctxf + cb + (long long)(r + 8) * DMODEL + d0) =
            pack2h(cacc[dt][2] * il1, cacc[dt][3] * il1);
    }

    // ======================= pass B: recompute S, write attn =======================
    // all warps passed the final syncthreads of pass A, so stage smem is free
    load_k(sS,         khb, 0, tid);
    load_k(sS + 16384, khb, 1, tid);

    for (int ci = 0; ci < NCH; ci++) {
        if (ci + 1 < NCH) { CP_WAIT1(); } else { CP_WAIT0(); }
        __syncthreads();
        const uint32_t st = sS + (ci & 1) * 16384;
        float* a0 = attn_w + (long long)r * NKV + ci * 128;
        float* a1 = a0 + 8 * NKV;

        #pragma unroll
        for (int nt = 0; nt < 8; nt++) {
            float s0[4] = {0.f, 0.f, 0.f, 0.f};
            float s1[4] = {0.f, 0.f, 0.f, 0.f};
            #pragma unroll
            for (int kk = 0; kk < 4; kk++) {
                const int colB = kk * 32 + ((lane & 8) ? 16 : 0);
                uint32_t off = SW128((uint32_t)(nt * 16 + rB) * 128 + colB);
                uint32_t bh[4];
                LDSM4(bh[0], bh[1], bh[2], bh[3], st + off);
                mma_f16(s0, qf[kk], bh);
                mma_f16(s1, qf[kk], bh + 2);
            }
            *(float2*)(a0 + (2*nt)   * 8 + c2) =
                make_float2(ex2(s0[0] * CE) * il0, ex2(s0[1] * CE) * il0);
            *(float2*)(a1 + (2*nt)   * 8 + c2) =
                make_float2(ex2(s0[2] * CE) * il1, ex2(s0[3] * CE) * il1);
            *(float2*)(a0 + (2*nt+1) * 8 + c2) =
                make_float2(ex2(s1[0] * CE) * il0, ex2(s1[1] * CE) * il0);
            *(float2*)(a1 + (2*nt+1) * 8 + c2) =
                make_float2(ex2(s1[2] * CE) * il1, ex2(s1[3] * CE) * il1);
        }

        __syncthreads();
        if (ci + 2 < NCH)
            load_k(sS + (ci & 1) * 16384, khb, ci + 2, tid);
    }
}

// ---------------- fp32 -> single fp16 ----------------
__global__ void __launch_bounds__(256)
k_cvt16(const float* __restrict__ x, f16* __restrict__ o)
{
    const long long i = ((long long)blockIdx.x * 256 + threadIdx.x) * 4;
    const float4 v = *(const float4*)(x + i);
    __half2 p0 = __floats2half2_rn(v.x, v.y);
    __half2 p1 = __floats2half2_rn(v.z, v.w);
    *(uint32_t*)(o + i)     = *reinterpret_cast<uint32_t*>(&p0);
    *(uint32_t*)(o + i + 2) = *reinterpret_cast<uint32_t*>(&p1);
}

// ---------------- layernorm -> single fp16 ----------------
__global__ void __launch_bounds__(256)
k_ln(const float* __restrict__ x, const float* __restrict__ g,
     const float* __restrict__ b, f16* __restrict__ o)
{
    __shared__ float r1[256], r2[256];
    const long long row = blockIdx.x;
    const float* p = x + row * (long long)DMODEL;
    const int t = threadIdx.x;

    float v[4]; float s = 0.0f, s2 = 0.0f;
    #pragma unroll
    for (int i = 0; i < 4; i++) {
        v[i] = p[t + i * 256];
        s += v[i]; s2 += v[i] * v[i];
    }
    r1[t] = s; r2[t] = s2; __syncthreads();
    for (int st = 128; st > 0; st >>= 1) {
        if (t < st) { r1[t] += r1[t + st]; r2[t] += r2[t + st]; }
        __syncthreads();
    }
    const float mu  = r1[0] * (1.0f / DMODEL);
    const float var = r2[0] * (1.0f / DMODEL) - mu * mu;
    const float inv = rsqrtf(var + 1e-5f);

    f16* po = o + row * (long long)DMODEL;
    #pragma unroll
    for (int i = 0; i < 4; i++) {
        const int c = t + i * 256;
        po[c] = __float2half_rn((v[i] - mu) * inv * g[c] + b[c]);
    }
}

// ---------------- host launch ----------------
static void* sym(const void* s) { void* p; cudaGetSymbolAddress(&p, s); return p; }

extern "C" void kernel_launch(void* const* d_in, const int* in_sizes, int n_in,
                              void* d_out, int out_size)
{
    const float* x    = (const float*)d_in[0];
    const float* q    = (const float*)d_in[1];
    const float* w_q  = (const float*)d_in[2];
    const float* b_q  = (const float*)d_in[3];
    const float* w_k  = (const float*)d_in[4];
    const float* b_k  = (const float*)d_in[5];
    const float* w_v  = (const float*)d_in[6];
    const float* b_v  = (const float*)d_in[7];
    const float* w_o  = (const float*)d_in[8];
    const float* b_o  = (const float*)d_in[9];
    const float* ln2g = (const float*)d_in[10];
    const float* ln2b = (const float*)d_in[11];
    const float* w1   = (const float*)d_in[12];
    const float* b1   = (const float*)d_in[13];
    const float* w2   = (const float*)d_in[14];
    const float* b2   = (const float*)d_in[15];

    float* out  = (float*)d_out;
    float* attn = out + (long long)BATCH * MQ * DMODEL;

    float* resid = (float*)sym(g_resid);
    f16 *qf=(f16*)sym(g_qf), *xf=(f16*)sym(g_xf);
    f16 *wqf=(f16*)sym(g_wqf), *wkf=(f16*)sym(g_wkf);
    f16 *wvf=(f16*)sym(g_wvf), *wof=(f16*)sym(g_wof);
    f16 *w1f=(f16*)sym(g_w1f), *w2f=(f16*)sym(g_w2f);
    f16 *qpf=(f16*)sym(g_qpf), *kpf=(f16*)sym(g_kpf), *vtf=(f16*)sym(g_vtf);
    f16 *ctxf=(f16*)sym(g_ctxf);
    f16 *hf=(f16*)sym(g_hf), *h1f=(f16*)sym(g_h1f);

    cudaFuncSetAttribute((const void*)k_gemm<0,OUT_F16>,   cudaFuncAttributeMaxDynamicSharedMemorySize, DSMEM1);
    cudaFuncSetAttribute((const void*)k_gemm<2,OUT_F16>,   cudaFuncAttributeMaxDynamicSharedMemorySize, DSMEM1);
    cudaFuncSetAttribute((const void*)k_gemm<0,OUT_VT>,    cudaFuncAttributeMaxDynamicSharedMemorySize, DSMEM1);
    cudaFuncSetAttribute((const void*)k_gemm<0,OUT_F32ADD>,cudaFuncAttributeMaxDynamicSharedMemorySize, DSMEM1);
    cudaFuncSetAttribute((const void*)k_attn, cudaFuncAttributeMaxDynamicSharedMemorySize, ATTN_SMEM);

    const dim3 blk(256);
    const dim3 dblk(DNT);
    #define C16(src, dst, nelem) k_cvt16<<<(int)((nelem) / 1024), blk>>>(src, dst)

    // conversions
    C16(x,   xf,  (size_t)BATCH*NKV*DMODEL);
    C16(w_v, wvf, (size_t)DMODEL*DMODEL);
    C16(w_k, wkf, (size_t)DMODEL*DMODEL);
    C16(q,   qf,  (size_t)BATCH*MQ*DMODEL);
    C16(w_q, wqf, (size_t)DMODEL*DMODEL);

    // V projection -> transposed single fp16
    k_gemm<0,OUT_VT><<<dim3(DMODEL/DTN, 64), dblk, DSMEM1>>>(xf, wvf, b_v, nullptr,
        nullptr, vtf, DMODEL, 0, 0);
    // K projection -> single fp16
    k_gemm<0,OUT_F16><<<dim3(DMODEL/DTN, 64), dblk, DSMEM1>>>(xf, wkf, b_k, nullptr,
        nullptr, kpf, DMODEL, DMODEL, 0);
    // Q projection -> single fp16
    k_gemm<0,OUT_F16><<<dim3(DMODEL/DTN, 32), dblk, DSMEM1>>>(qf, wqf, b_q, nullptr,
        nullptr, qpf, DMODEL, DMODEL, 0);

    // fused two-pass attention
    k_attn<<<dim3(ZHB, MQ/128), blk, ATTN_SMEM>>>(qpf, kpf, vtf, attn, ctxf);

    // remaining weight conversions
    C16(w_o, wof, (size_t)DMODEL*DMODEL);
    C16(w1,  w1f, (size_t)DMLP*DMODEL);
    C16(w2,  w2f, (size_t)DMODEL*DMLP);

    // resid = ctx @ w_o^T + b_o + q
    k_gemm<0,OUT_F32ADD><<<dim3(DMODEL/DTN, 32), dblk, DSMEM1>>>(ctxf, wof, b_o, q,
        resid, nullptr, DMODEL, DMODEL, DMODEL);

    // h = LN(resid) -> fp16
    k_ln<<<BATCH*MQ, blk>>>(resid, ln2g, ln2b, hf);

    // h1 = gelu(h @ w1^T + b1) -> fp16
    k_gemm<2,OUT_F16><<<dim3(DMLP/DTN, 32), dblk, DSMEM1>>>(hf, w1f, b1, nullptr,
        nullptr, h1f, DMODEL, DMLP, 0);

    // out = h1 @ w2^T + b2 + resid
    k_gemm<0,OUT_F32ADD><<<dim3(DMODEL/DTN, 32), dblk, DSMEM1>>>(h1f, w2f, b2, resid,
        out, nullptr, DMLP, DMODEL, DMODEL);

    #undef C16
}

// round 15
// speedup vs baseline: 1.6553x; 1.0278x over previous
#include <cuda_runtime.h>
#include <cuda_fp16.h>
#include <math.h>
#include <stdint.h>

// ---------------- problem constants ----------------
#define BATCH  4
#define MQ     1024
#define NKV    2048
#define DMODEL 1024
#define NHEAD  16
#define HDIM   64
#define DMLP   4096
#define ZHB    (NHEAD*BATCH)

typedef __half f16;

// ---------------- scratch (device globals; no allocs allowed) ----------------
__device__ __align__(1024) float g_resid[(size_t)BATCH*MQ*DMODEL];

__device__ __align__(1024) f16 g_qf [(size_t)BATCH*MQ*DMODEL];
__device__ __align__(1024) f16 g_xf [(size_t)BATCH*NKV*DMODEL];
__device__ __align__(1024) f16 g_wqf[(size_t)DMODEL*DMODEL];
__device__ __align__(1024) f16 g_wkf[(size_t)DMODEL*DMODEL];
__device__ __align__(1024) f16 g_wvf[(size_t)DMODEL*DMODEL];
__device__ __align__(1024) f16 g_wof[(size_t)DMODEL*DMODEL];
__device__ __align__(1024) f16 g_w1f[(size_t)DMLP*DMODEL];
__device__ __align__(1024) f16 g_w2f[(size_t)DMODEL*DMLP];
__device__ __align__(1024) f16 g_qpf[(size_t)BATCH*MQ*DMODEL];
__device__ __align__(1024) f16 g_kpf[(size_t)BATCH*NKV*DMODEL];
__device__ __align__(1024) f16 g_vtf[(size_t)ZHB*HDIM*NKV];
__device__ __align__(1024) f16 g_ctxf[(size_t)BATCH*MQ*DMODEL];
__device__ __align__(1024) f16 g_hf [(size_t)BATCH*MQ*DMODEL];
__device__ __align__(1024) f16 g_h1f[(size_t)BATCH*MQ*DMLP];

// ---------------- helpers ----------------
#define SW128(o) ((uint32_t)(o) ^ ((((uint32_t)(o)) >> 3) & 0x70u))

__device__ __forceinline__ uint32_t smem_u32(const void* p) {
    return (uint32_t)__cvta_generic_to_shared(p);
}

__device__ __forceinline__ void cp16(uint32_t dst, const void* src) {
    asm volatile("cp.async.cg.shared.global [%0], [%1], 16;" :: "r"(dst), "l"(src));
}
#define CP_COMMIT() asm volatile("cp.async.commit_group;" ::: "memory")
#define CP_WAIT0()  asm volatile("cp.async.wait_group 0;" ::: "memory")
#define CP_WAIT1()  asm volatile("cp.async.wait_group 1;" ::: "memory")
#define CP_WAIT2()  asm volatile("cp.async.wait_group 2;" ::: "memory")

#define LDSM4(r0, r1, r2, r3, addr) \
    asm volatile("ldmatrix.sync.aligned.m8n8.x4.shared.b16 {%0,%1,%2,%3}, [%4];" \
        : "=r"(r0), "=r"(r1), "=r"(r2), "=r"(r3) : "r"(addr))

__device__ __forceinline__ void mma_f16(float* c, const uint32_t* a, const uint32_t* b) {
    asm volatile(
        "mma.sync.aligned.m16n8k16.row.col.f32.f16.f16.f32 "
        "{%0,%1,%2,%3}, {%4,%5,%6,%7}, {%8,%9}, {%0,%1,%2,%3};"
        : "+f"(c[0]), "+f"(c[1]), "+f"(c[2]), "+f"(c[3])
        : "r"(a[0]), "r"(a[1]), "r"(a[2]), "r"(a[3]), "r"(b[0]), "r"(b[1]));
}

__device__ __forceinline__ float ex2(float x) {
    float r;
    asm("ex2.approx.f32 %0, %1;" : "=f"(r) : "f"(x));
    return r;
}

__device__ __forceinline__ float gelu_exact(float v) {
    return 0.5f * v * (1.0f + erff(v * 0.70710678118654752440f));
}

__device__ __forceinline__ uint32_t pack2h(float e0, float e1) {
    __half2 hp = __floats2half2_rn(e0, e1);
    return *reinterpret_cast<uint32_t*>(&hp);
}

// ============================================================================
//   single-term fp16 GEMM: 128x128 CTA tile, 8 warps (4x2), MI=2 NI=8,
//   32KB stages, 2 CTAs/SM.  Higher fill intensity (64 FLOP/B).
// ============================================================================
#define DNT 256
#define DTN 128
#define OUT_F32ADD 0
#define OUT_F16    1
#define OUT_VT     2

template<int EPI, int OUT>
__device__ void tc_gemm1(
    const f16* __restrict__ A, const f16* __restrict__ Bs,
    const float* __restrict__ bias, const float* __restrict__ Dadd,
    float* __restrict__ C, f16* __restrict__ Cf,
    int K, int lda, int ldb, int ldc, int ldd)
{
    extern __shared__ char smem[];
    constexpr int TN = DTN;
    constexpr int A_BYTES = 128 * 128;           // 16384
    constexpr int B_BYTES = TN * 128;            // 16384
    constexpr int STAGE   = A_BYTES + B_BYTES;   // 32768
    constexpr int MI = 2;
    constexpr int NI = 8;

    const uint32_t sb = smem_u32(smem);
    const int tid  = threadIdx.x;
    const int wid  = tid >> 5;
    const int lane = tid & 31;
    const int m0 = blockIdx.y * 128;
    const int n0 = blockIdx.x * TN;
    const int wm0 = (wid >> 1) * 32;     // 4 warp-rows
    const int wn0 = (wid & 1) * 64;      // 2 warp-cols

    float acc[MI][NI][4];
    #pragma unroll
    for (int mi = 0; mi < MI; mi++)
        #pragma unroll
        for (int ni = 0; ni < NI; ni++)
            #pragma unroll
            for (int e = 0; e < 4; e++) acc[mi][ni][e] = 0.0f;

    auto load1 = [&](uint32_t st, long long kc) {
        #pragma unroll
        for (int it = 0; it < 4; it++) {
            int idx = tid + it * 256;
            int r = idx >> 3, c = idx & 7;
            uint32_t so = SW128(r * 128 + c * 16);
            cp16(st + so, A + (long long)(m0 + r) * lda + kc + c * 8);
        }
        #pragma unroll
        for (int it = 0; it < 4; it++) {
            int idx = tid + it * 256;
            int r = idx >> 3, c = idx & 7;
            uint32_t so = SW128(r * 128 + c * 16);
            cp16(st + A_BYTES + so, Bs + (long long)(n0 + r) * ldb + kc + c * 8);
        }
        CP_COMMIT();
    };

    const int NC = K >> 6;
    load1(sb, 0);
    if (NC > 1) load1(sb + STAGE, 64);

    for (int i = 0; i < NC; i++) {
        if (i + 1 < NC) { CP_WAIT1(); } else { CP_WAIT0(); }
        __syncthreads();

        const uint32_t st = sb + (i & 1) * STAGE;
        #pragma unroll
        for (int kk = 0; kk < 4; kk++) {
            uint32_t ah[MI][4], bh[NI][2];
            const int colA = kk * 32 + ((lane & 16) ? 16 : 0);
            const int rA   = lane & 15;
            #pragma unroll
            for (int mi = 0; mi < MI; mi++) {
                uint32_t off = SW128((uint32_t)(wm0 + mi * 16 + rA) * 128 + colA);
                LDSM4(ah[mi][0], ah[mi][1], ah[mi][2], ah[mi][3], st + off);
            }
            const int colB = kk * 32 + ((lane & 8) ? 16 : 0);
            const int rB   = (lane & 7) + ((lane & 16) ? 8 : 0);
            #pragma unroll
            for (int nj = 0; nj < 4; nj++) {
                uint32_t off = SW128((uint32_t)(wn0 + nj * 16 + rB) * 128 + colB);
                LDSM4(bh[nj*2][0], bh[nj*2][1], bh[nj*2+1][0], bh[nj*2+1][1],
                      st + A_BYTES + off);
            }
            #pragma unroll
            for (int mi = 0; mi < MI; mi++)
                #pragma unroll
                for (int ni = 0; ni < NI; ni++)
                    mma_f16(acc[mi][ni], ah[mi], bh[ni]);
        }
        __syncthreads();
        if (i + 2 < NC) load1(sb + (i & 1) * STAGE, (long long)(i + 2) * 64);
    }

    constexpr int LDS = (OUT == OUT_VT) ? (TN + 1) : (TN + 8);
    float* sOut = (float*)smem;
    __syncthreads();

    #pragma unroll
    for (int mi = 0; mi < MI; mi++) {
        const int r0 = wm0 + mi * 16 + (lane >> 2);
        #pragma unroll
        for (int ni = 0; ni < NI; ni++) {
            const int c0 = wn0 + ni * 8 + (lane & 3) * 2;
            sOut[r0 * LDS + c0]           = acc[mi][ni][0];
            sOut[r0 * LDS + c0 + 1]       = acc[mi][ni][1];
            sOut[(r0 + 8) * LDS + c0]     = acc[mi][ni][2];
            sOut[(r0 + 8) * LDS + c0 + 1] = acc[mi][ni][3];
        }
    }
    __syncthreads();

    if (OUT == OUT_VT) {
        const int bb = m0 / NKV;
        const int nb = m0 % NKV;
        const int colw = tid >> 5;
        #pragma unroll
        for (int cp = 0; cp < TN / 8; cp++) {
            const int col = colw + cp * 8;
            const int e = n0 + col;
            const int hh2 = e >> 6, dd = e & 63;
            const long long base =
                ((long long)(hh2 * BATCH + bb) * HDIM + dd) * NKV + nb;
            const float bv = bias[e];
            #pragma unroll
            for (int rh = 0; rh < 2; rh++) {
                const int row0 = rh * 64 + 2 * lane;
                const float v0 = sOut[row0       * LDS + col] + bv;
                const float v1 = sOut[(row0 + 1) * LDS + col] + bv;
                *(uint32_t*)(Cf + base + row0) = pack2h(v0, v1);
            }
        }
        return;
    }

    const int c = tid & (TN - 1);
    const int rs = tid / TN;
    const int n = n0 + c;
    #pragma unroll 4
    for (int rr = 0; rr < 128; rr += 2) {
        const int r = rr + rs;
        float v = sOut[r * LDS + c] + bias[n];
        const long long o = (long long)(m0 + r) * ldc + n;
        if (OUT == OUT_F32ADD) {
            C[o] = v + Dadd[(long long)(m0 + r) * ldd + n];
        } else {
            if (EPI == 2) v = gelu_exact(v);
            Cf[o] = __float2half_rn(v);
        }
    }
}

template<int EPI, int OUT>
__global__ void __launch_bounds__(DNT, 2)
k_gemm(const f16* A, const f16* Bs,
       const float* bias, const float* Dadd,
       float* C, f16* Cf, int K, int ldc, int ldd)
{
    tc_gemm1<EPI, OUT>(A, Bs, bias, Dadd, C, Cf, K, K, K, ldc, ldd);
}

#define DSMEM1 69632   // max(2 stages 65536, epilogue 128*136*4)

// ============================================================================
//   fused two-pass attention (unchanged from round 14)
// ============================================================================
#define ATTN_SMEM (16384 + 2*32768)
#define NCH (NKV/128)

__device__ __forceinline__ void load_kv(
    uint32_t st, const f16* __restrict__ kp, const f16* __restrict__ vt,
    int ci, int tid)
{
    #pragma unroll
    for (int it = 0; it < 4; it++) {
        int idx = tid + it * 256;
        int r = idx >> 3, c = idx & 7;
        uint32_t so = SW128((uint32_t)r * 128 + c * 16);
        cp16(st + so, kp + (long long)(ci * 128 + r) * DMODEL + c * 8);
    }
    #pragma unroll
    for (int it = 0; it < 4; it++) {
        int idx = tid + it * 256;
        int hf = idx >> 9, d = (idx >> 3) & 63, c = idx & 7;
        uint32_t so = (uint32_t)hf * 8192 + SW128((uint32_t)d * 128 + c * 16);
        cp16(st + 16384 + so, vt + (long long)d * NKV + ci * 128 + hf * 64 + c * 8);
    }
    CP_COMMIT();
}

__device__ __forceinline__ void load_k(
    uint32_t st, const f16* __restrict__ kp, int ci, int tid)
{
    #pragma unroll
    for (int it = 0; it < 4; it++) {
        int idx = tid + it * 256;
        int r = idx >> 3, c = idx & 7;
        uint32_t so = SW128((uint32_t)r * 128 + c * 16);
        cp16(st + so, kp + (long long)(ci * 128 + r) * DMODEL + c * 8);
    }
    CP_COMMIT();
}

__global__ void __launch_bounds__(256, 2)
k_attn(const f16* __restrict__ qpf, const f16* __restrict__ kpf,
       const f16* __restrict__ vtf,
       float* __restrict__ attn, f16* __restrict__ ctxf)
{
    extern __shared__ char smem[];
    const uint32_t sb = smem_u32(smem);
    const int tid = threadIdx.x, wid = tid >> 5, lane = tid & 31;
    const int z  = blockIdx.x;            // h*BATCH + b
    const int h  = z / BATCH, b = z % BATCH;
    const int m0 = blockIdx.y * 128;
    const int wm0 = wid * 16;

    const f16* khb = kpf + (long long)b * NKV * DMODEL + h * HDIM;
    const f16* vtb = vtf + (long long)z * HDIM * NKV;
    float* attn_w = attn + ((long long)z * MQ + m0 + wm0) * NKV;

    const uint32_t sQ = sb;
    const uint32_t sS = sb + 16384;

    {
        const f16* q0 = qpf + ((long long)(b * MQ + m0)) * DMODEL + h * HDIM;
        #pragma unroll
        for (int it = 0; it < 4; it++) {
            int idx = tid + it * 256;
            int r = idx >> 3, c = idx & 7;
            uint32_t so = SW128((uint32_t)r * 128 + c * 16);
            cp16(sQ + so, q0 + (long long)r * DMODEL + c * 8);
        }
        CP_COMMIT();
    }
    load_kv(sS,         khb, vtb, 0, tid);
    load_kv(sS + 32768, khb, vtb, 1, tid);

    CP_WAIT2();
    __syncthreads();

    uint32_t qf[4][4];
    {
        const int rA = lane & 15;
        #pragma unroll
        for (int kk = 0; kk < 4; kk++) {
            const int colA = kk * 32 + ((lane & 16) ? 16 : 0);
            uint32_t off = SW128((uint32_t)(wm0 + rA) * 128 + colA);
            LDSM4(qf[kk][0], qf[kk][1], qf[kk][2], qf[kk][3], sQ + off);
        }
    }

    float cacc[8][4];
    #pragma unroll
    for (int i = 0; i < 8; i++)
        #pragma unroll
        for (int e = 0; e < 4; e++) cacc[i][e] = 0.0f;
    float lp0 = 0.0f, lp1 = 0.0f;

    const int rB   = (lane & 7) + ((lane & 16) ? 8 : 0);
    const int r    = lane >> 2;
    const int c2   = (lane & 3) * 2;
    const float CE = 0.125f * 1.4426950408889634f;

    // ======================= pass A: lp + PV =======================
    for (int ci = 0; ci < NCH; ci++) {
        if (ci + 1 < NCH) { CP_WAIT1(); } else { CP_WAIT0(); }
        __syncthreads();
        const uint32_t st = sS + (ci & 1) * 32768;

        #pragma unroll
        for (int nt = 0; nt < 8; nt++) {
            float s0[4] = {0.f, 0.f, 0.f, 0.f};
            float s1[4] = {0.f, 0.f, 0.f, 0.f};
            #pragma unroll
            for (int kk = 0; kk < 4; kk++) {
                const int colB = kk * 32 + ((lane & 8) ? 16 : 0);
                uint32_t off = SW128((uint32_t)(nt * 16 + rB) * 128 + colB);
                uint32_t bh[4];
                LDSM4(bh[0], bh[1], bh[2], bh[3], st + off);
                mma_f16(s0, qf[kk], bh);
                mma_f16(s1, qf[kk], bh + 2);
            }

            const float p0 = ex2(s0[0] * CE), p1 = ex2(s0[1] * CE);
            const float p2 = ex2(s0[2] * CE), p3 = ex2(s0[3] * CE);
            const float p4 = ex2(s1[0] * CE), p5 = ex2(s1[1] * CE);
            const float p6 = ex2(s1[2] * CE), p7 = ex2(s1[3] * CE);
            lp0 += p0 + p1 + p4 + p5;
            lp1 += p2 + p3 + p6 + p7;

            uint32_t ah[4];
            ah[0] = pack2h(p0, p1);
            ah[1] = pack2h(p2, p3);
            ah[2] = pack2h(p4, p5);
            ah[3] = pack2h(p6, p7);

            const int hf = nt >> 2;
            const int colB = (nt & 3) * 32 + ((lane & 8) ? 16 : 0);
            const uint32_t v_base = st + 16384 + hf * 8192;
            #pragma unroll
            for (int dt = 0; dt < 4; dt++) {
                uint32_t off = SW128((uint32_t)(dt * 16 + rB) * 128 + colB);
                uint32_t bh[4];
                LDSM4(bh[0], bh[1], bh[2], bh[3], v_base + off);
                mma_f16(cacc[2*dt],   ah, bh);
                mma_f16(cacc[2*dt+1], ah, bh + 2);
            }
        }

        __syncthreads();
        if (ci + 2 < NCH)
            load_kv(sS + (ci & 1) * 32768, khb, vtb, ci + 2, tid);
    }

    lp0 += __shfl_xor_sync(0xFFFFFFFFu, lp0, 1);
    lp0 += __shfl_xor_sync(0xFFFFFFFFu, lp0, 2);
    lp1 += __shfl_xor_sync(0xFFFFFFFFu, lp1, 1);
    lp1 += __shfl_xor_sync(0xFFFFFFFFu, lp1, 2);
    const float il0 = 1.0f / lp0, il1 = 1.0f / lp1;

    const long long cb = ((long long)(b * MQ + m0 + wm0)) * DMODEL + h * HDIM;
    #pragma unroll
    for (int dt = 0; dt < 8; dt++) {
        const int d0 = dt * 8 + c2;
        *(uint32_t*)(ctxf + cb + (long long)r * DMODEL + d0) =
            pack2h(cacc[dt][0] * il0, cacc[dt][1] * il0);
        *(uint32_t*)(ctxf + cb + (long long)(r + 8) * DMODEL + d0) =
            pack2h(cacc[dt][2] * il1, cacc[dt][3] * il1);
    }

    // ======================= pass B: recompute S, write attn =======================
    load_k(sS,         khb, 0, tid);
    load_k(sS + 16384, khb, 1, tid);

    for (int ci = 0; ci < NCH; ci++) {
        if (ci + 1 < NCH) { CP_WAIT1(); } else { CP_WAIT0(); }
        __syncthreads();
        const uint32_t st = sS + (ci & 1) * 16384;
        float* a0 = attn_w + (long long)r * NKV + ci * 128;
        float* a1 = a0 + 8 * NKV;

        #pragma unroll
        for (int nt = 0; nt < 8; nt++) {
            float s0[4] = {0.f, 0.f, 0.f, 0.f};
            float s1[4] = {0.f, 0.f, 0.f, 0.f};
            #pragma unroll
            for (int kk = 0; kk < 4; kk++) {
                const int colB = kk * 32 + ((lane & 8) ? 16 : 0);
                uint32_t off = SW128((uint32_t)(nt * 16 + rB) * 128 + colB);
                uint32_t bh[4];
                LDSM4(bh[0], bh[1], bh[2], bh[3], st + off);
                mma_f16(s0, qf[kk], bh);
                mma_f16(s1, qf[kk], bh + 2);
            }
            *(float2*)(a0 + (2*nt)   * 8 + c2) =
                make_float2(ex2(s0[0] * CE) * il0, ex2(s0[1] * CE) * il0);
            *(float2*)(a1 + (2*nt)   * 8 + c2) =
                make_float2(ex2(s0[2] * CE) * il1, ex2(s0[3] * CE) * il1);
            *(float2*)(a0 + (2*nt+1) * 8 + c2) =
                make_float2(ex2(s1[0] * CE) * il0, ex2(s1[1] * CE) * il0);
            *(float2*)(a1 + (2*nt+1) * 8 + c2) =
                make_float2(ex2(s1[2] * CE) * il1, ex2(s1[3] * CE) * il1);
        }

        __syncthreads();
        if (ci + 2 < NCH)
            load_k(sS + (ci & 1) * 16384, khb, ci + 2, tid);
    }
}

// ---------------- fp32 -> single fp16 ----------------
__global__ void __launch_bounds__(256)
k_cvt16(const float* __restrict__ x, f16* __restrict__ o)
{
    const long long i = ((long long)blockIdx.x * 256 + threadIdx.x) * 4;
    const float4 v = *(const float4*)(x + i);
    __half2 p0 = __floats2half2_rn(v.x, v.y);
    __half2 p1 = __floats2half2_rn(v.z, v.w);
    *(uint32_t*)(o + i)     = *reinterpret_cast<uint32_t*>(&p0);
    *(uint32_t*)(o + i + 2) = *reinterpret_cast<uint32_t*>(&p1);
}

// ---------------- layernorm -> single fp16 ----------------
__global__ void __launch_bounds__(256)
k_ln(const float* __restrict__ x, const float* __restrict__ g,
     const float* __restrict__ b, f16* __restrict__ o)
{
    __shared__ float r1[256], r2[256];
    const long long row = blockIdx.x;
    const float* p = x + row * (long long)DMODEL;
    const int t = threadIdx.x;

    float v[4]; float s = 0.0f, s2 = 0.0f;
    #pragma unroll
    for (int i = 0; i < 4; i++) {
        v[i] = p[t + i * 256];
        s += v[i]; s2 += v[i] * v[i];
    }
    r1[t] = s; r2[t] = s2; __syncthreads();
    for (int st = 128; st > 0; st >>= 1) {
        if (t < st) { r1[t] += r1[t + st]; r2[t] += r2[t + st]; }
        __syncthreads();
    }
    const float mu  = r1[0] * (1.0f / DMODEL);
    const float var = r2[0] * (1.0f / DMODEL) - mu * mu;
    const float inv = rsqrtf(var + 1e-5f);

    f16* po = o + row * (long long)DMODEL;
    #pragma unroll
    for (int i = 0; i < 4; i++) {
        const int c = t + i * 256;
        po[c] = __float2half_rn((v[i] - mu) * inv * g[c] + b[c]);
    }
}

// ---------------- host launch ----------------
static void* sym(const void* s) { void* p; cudaGetSymbolAddress(&p, s); return p; }

extern "C" void kernel_launch(void* const* d_in, const int* in_sizes, int n_in,
                              void* d_out, int out_size)
{
    const float* x    = (const float*)d_in[0];
    const float* q    = (const float*)d_in[1];
    const float* w_q  = (const float*)d_in[2];
    const float* b_q  = (const float*)d_in[3];
    const float* w_k  = (const float*)d_in[4];
    const float* b_k  = (const float*)d_in[5];
    const float* w_v  = (const float*)d_in[6];
    const float* b_v  = (const float*)d_in[7];
    const float* w_o  = (const float*)d_in[8];
    const float* b_o  = (const float*)d_in[9];
    const float* ln2g = (const float*)d_in[10];
    const float* ln2b = (const float*)d_in[11];
    const float* w1   = (const float*)d_in[12];
    const float* b1   = (const float*)d_in[13];
    const float* w2   = (const float*)d_in[14];
    const float* b2   = (const float*)d_in[15];

    float* out  = (float*)d_out;
    float* attn = out + (long long)BATCH * MQ * DMODEL;

    float* resid = (float*)sym(g_resid);
    f16 *qf=(f16*)sym(g_qf), *xf=(f16*)sym(g_xf);
    f16 *wqf=(f16*)sym(g_wqf), *wkf=(f16*)sym(g_wkf);
    f16 *wvf=(f16*)sym(g_wvf), *wof=(f16*)sym(g_wof);
    f16 *w1f=(f16*)sym(g_w1f), *w2f=(f16*)sym(g_w2f);
    f16 *qpf=(f16*)sym(g_qpf), *kpf=(f16*)sym(g_kpf), *vtf=(f16*)sym(g_vtf);
    f16 *ctxf=(f16*)sym(g_ctxf);
    f16 *hf=(f16*)sym(g_hf), *h1f=(f16*)sym(g_h1f);

    cudaFuncSetAttribute((const void*)k_gemm<0,OUT_F16>,   cudaFuncAttributeMaxDynamicSharedMemorySize, DSMEM1);
    cudaFuncSetAttribute((const void*)k_gemm<2,OUT_F16>,   cudaFuncAttributeMaxDynamicSharedMemorySize, DSMEM1);
    cudaFuncSetAttribute((const void*)k_gemm<0,OUT_VT>,    cudaFuncAttributeMaxDynamicSharedMemorySize, DSMEM1);
    cudaFuncSetAttribute((const void*)k_gemm<0,OUT_F32ADD>,cudaFuncAttributeMaxDynamicSharedMemorySize, DSMEM1);
    cudaFuncSetAttribute((const void*)k_attn, cudaFuncAttributeMaxDynamicSharedMemorySize, ATTN_SMEM);

    const dim3 blk(256);
    const dim3 dblk(DNT);
    #define C16(src, dst, nelem) k_cvt16<<<(int)((nelem) / 1024), blk>>>(src, dst)

    // conversions
    C16(x,   xf,  (size_t)BATCH*NKV*DMODEL);
    C16(w_v, wvf, (size_t)DMODEL*DMODEL);
    C16(w_k, wkf, (size_t)DMODEL*DMODEL);
    C16(q,   qf,  (size_t)BATCH*MQ*DMODEL);
    C16(w_q, wqf, (size_t)DMODEL*DMODEL);

    // V projection -> transposed single fp16
    k_gemm<0,OUT_VT><<<dim3(DMODEL/DTN, 64), dblk, DSMEM1>>>(xf, wvf, b_v, nullptr,
        nullptr, vtf, DMODEL, 0, 0);
    // K projection -> single fp16
    k_gemm<0,OUT_F16><<<dim3(DMODEL/DTN, 64), dblk, DSMEM1>>>(xf, wkf, b_k, nullptr,
        nullptr, kpf, DMODEL, DMODEL, 0);
    // Q projection -> single fp16
    k_gemm<0,OUT_F16><<<dim3(DMODEL/DTN, 32), dblk, DSMEM1>>>(qf, wqf, b_q, nullptr,
        nullptr, qpf, DMODEL, DMODEL, 0);

    // fused two-pass attention
    k_attn<<<dim3(ZHB, MQ/128), blk, ATTN_SMEM>>>(qpf, kpf, vtf, attn, ctxf);

    // remaining weight conversions
    C16(w_o, wof, (size_t)DMODEL*DMODEL);
    C16(w1,  w1f, (size_t)DMLP*DMODEL);
    C16(w2,  w2f, (size_t)DMODEL*DMLP);

    // resid = ctx @ w_o^T + b_o + q
    k_gemm<0,OUT_F32ADD><<<dim3(DMODEL/DTN, 32), dblk, DSMEM1>>>(ctxf, wof, b_o, q,
        resid, nullptr, DMODEL, DMODEL, DMODEL);

    // h = LN(resid) -> fp16
    k_ln<<<BATCH*MQ, blk>>>(resid, ln2g, ln2b, hf);

    // h1 = gelu(h @ w1^T + b1) -> fp16
    k_gemm<2,OUT_F16><<<dim3(DMLP/DTN, 32), dblk, DSMEM1>>>(hf, w1f, b1, nullptr,
        nullptr, h1f, DMODEL, DMLP, 0);

    // out = h1 @ w2^T + b2 + resid
    k_gemm<0,OUT_F32ADD><<<dim3(DMODEL/DTN, 32), dblk, DSMEM1>>>(h1f, w2f, b2, resid,
        out, nullptr, DMLP, DMODEL, DMODEL);

    #undef C16
}